// round 13
// baseline (speedup 1.0000x reference)
#include <cuda_runtime.h>
#include <cuda_fp16.h>

// ---------------- problem constants ----------------
#define D_     256
#define NH_    8
#define DH_    32
#define NS_    12
#define NP_    4
#define HB_    200
#define WB_    200
#define V_     (HB_*WB_)       // 40000
#define BS_    2
#define A_     256
#define M_     6
#define NQ_    (A_*M_)         // 1536
#define ROWS_  (BS_*NQ_)       // 3072
#define LN_EPS 1e-5f

#define BK_    32
#define ASTR_  68              // padded m-stride: 2-way (vs 4-way) store conflicts
#define KSPLIT 4               // split-K factor for the out-projection GEMM

// ---------------- device scratch (static, allocation-free) ----------------
__device__ __align__(16) __half g_vimg[(size_t)BS_*NH_*V_*DH_];    // fp16 [b][h][pix][dh]
__device__ __align__(16) float g_off [(size_t)ROWS_*768];          // offsets GEMM out
__device__ __align__(16) float g_aw  [(size_t)ROWS_*384];          // attn logits GEMM out
__device__ __align__(16) float4 g_scw[(size_t)ROWS_*NS_*NH_*NP_];  // (x, y, weight, pad)
__device__ __align__(16) float g_samp[(size_t)ROWS_*NS_*D_];       // sampled (3072, 3072)
__device__ __align__(16) float g_opart[(size_t)KSPLIT*ROWS_*D_];   // split-K partials

// ---------------- generic SGEMM: C = (A [+Aadd]) @ B + bias ----------------
// A: M x K row-major, B: K x N row-major. M%64==0, N%64==0, K%32==0.
__global__ __launch_bounds__(256) void sgemm_bias(
    const float* __restrict__ A, const float* __restrict__ Aadd,
    const float* __restrict__ B, const float* __restrict__ bias,
    float* __restrict__ C, int M, int N, int K)
{
    __shared__ float As[BK_][ASTR_];
    __shared__ float Bs[BK_][64];
    const int tid = threadIdx.x;
    const int tx = tid & 15, ty = tid >> 4;
    const int row0 = blockIdx.y * 64;
    const int col0 = blockIdx.x * 64;
    const int a_m = tid >> 3, a_k = (tid & 7) << 2;
    const int b_k = tid >> 4, b_n = (tid & 15) << 2;

    float acc[4][4] = {};
    for (int k0 = 0; k0 < K; k0 += BK_) {
        float4 av0 = *reinterpret_cast<const float4*>(&A[(size_t)(row0 + a_m) * K + k0 + a_k]);
        float4 av1 = *reinterpret_cast<const float4*>(&A[(size_t)(row0 + a_m + 32) * K + k0 + a_k]);
        if (Aadd) {
            float4 p0 = *reinterpret_cast<const float4*>(&Aadd[(size_t)(row0 + a_m) * K + k0 + a_k]);
            av0.x += p0.x; av0.y += p0.y; av0.z += p0.z; av0.w += p0.w;
            float4 p1 = *reinterpret_cast<const float4*>(&Aadd[(size_t)(row0 + a_m + 32) * K + k0 + a_k]);
            av1.x += p1.x; av1.y += p1.y; av1.z += p1.z; av1.w += p1.w;
        }
        As[a_k + 0][a_m] = av0.x;
        As[a_k + 1][a_m] = av0.y;
        As[a_k + 2][a_m] = av0.z;
        As[a_k + 3][a_m] = av0.w;
        As[a_k + 0][a_m + 32] = av1.x;
        As[a_k + 1][a_m + 32] = av1.y;
        As[a_k + 2][a_m + 32] = av1.z;
        As[a_k + 3][a_m + 32] = av1.w;
        *reinterpret_cast<float4*>(&Bs[b_k][b_n]) =
            *reinterpret_cast<const float4*>(&B[(size_t)(k0 + b_k) * N + col0 + b_n]);
        *reinterpret_cast<float4*>(&Bs[b_k + 16][b_n]) =
            *reinterpret_cast<const float4*>(&B[(size_t)(k0 + b_k + 16) * N + col0 + b_n]);
        __syncthreads();
        #pragma unroll
        for (int k = 0; k < BK_; k++) {
            float am[4], bn[4];
            #pragma unroll
            for (int i = 0; i < 4; i++) am[i] = As[k][ty * 4 + i];
            #pragma unroll
            for (int j = 0; j < 4; j++) bn[j] = Bs[k][tx * 4 + j];
            #pragma unroll
            for (int i = 0; i < 4; i++)
                #pragma unroll
                for (int j = 0; j < 4; j++) acc[i][j] += am[i] * bn[j];
        }
        __syncthreads();
    }
    const int col = col0 + tx * 4;
    float4 bv = *reinterpret_cast<const float4*>(&bias[col]);
    #pragma unroll
    for (int i = 0; i < 4; i++) {
        int row = row0 + ty * 4 + i;
        float4 o = make_float4(acc[i][0] + bv.x, acc[i][1] + bv.y,
                               acc[i][2] + bv.z, acc[i][3] + bv.w);
        *reinterpret_cast<float4*>(&C[(size_t)row * N + col]) = o;
    }
}

// ---------------- split-K out-projection: partial[z] = A[:,z*768:+768] @ B[z*768:,:] ----
__global__ __launch_bounds__(256) void gemm_out_splitk(
    const float* __restrict__ B)
{
    __shared__ float As[BK_][ASTR_];
    __shared__ float Bs[BK_][64];
    const int tid = threadIdx.x;
    const int tx = tid & 15, ty = tid >> 4;
    const int row0 = blockIdx.y * 64;
    const int col0 = blockIdx.x * 64;
    const int slice = blockIdx.z;
    const int kbase = slice * (3072 / KSPLIT);    // 768 per slice
    const int a_m = tid >> 3, a_k = (tid & 7) << 2;
    const int b_k = tid >> 4, b_n = (tid & 15) << 2;
    float* __restrict__ C = g_opart + (size_t)slice * ROWS_ * D_;

    float acc[4][4] = {};
    for (int kk = 0; kk < 3072 / KSPLIT; kk += BK_) {
        const int k0 = kbase + kk;
        float4 av0 = *reinterpret_cast<const float4*>(&g_samp[(size_t)(row0 + a_m) * 3072 + k0 + a_k]);
        float4 av1 = *reinterpret_cast<const float4*>(&g_samp[(size_t)(row0 + a_m + 32) * 3072 + k0 + a_k]);
        As[a_k + 0][a_m] = av0.x;
        As[a_k + 1][a_m] = av0.y;
        As[a_k + 2][a_m] = av0.z;
        As[a_k + 3][a_m] = av0.w;
        As[a_k + 0][a_m + 32] = av1.x;
        As[a_k + 1][a_m + 32] = av1.y;
        As[a_k + 2][a_m + 32] = av1.z;
        As[a_k + 3][a_m + 32] = av1.w;
        *reinterpret_cast<float4*>(&Bs[b_k][b_n]) =
            *reinterpret_cast<const float4*>(&B[(size_t)(k0 + b_k) * 256 + col0 + b_n]);
        *reinterpret_cast<float4*>(&Bs[b_k + 16][b_n]) =
            *reinterpret_cast<const float4*>(&B[(size_t)(k0 + b_k + 16) * 256 + col0 + b_n]);
        __syncthreads();
        #pragma unroll
        for (int k = 0; k < BK_; k++) {
            float am[4], bn[4];
            #pragma unroll
            for (int i = 0; i < 4; i++) am[i] = As[k][ty * 4 + i];
            #pragma unroll
            for (int j = 0; j < 4; j++) bn[j] = Bs[k][tx * 4 + j];
            #pragma unroll
            for (int i = 0; i < 4; i++)
                #pragma unroll
                for (int j = 0; j < 4; j++) acc[i][j] += am[i] * bn[j];
        }
        __syncthreads();
    }
    const int col = col0 + tx * 4;
    #pragma unroll
    for (int i = 0; i < 4; i++) {
        int row = row0 + ty * 4 + i;
        *reinterpret_cast<float4*>(&C[(size_t)row * 256 + col]) =
            make_float4(acc[i][0], acc[i][1], acc[i][2], acc[i][3]);
    }
}

// ---------------- value projection GEMM with fused fp16 layout scatter ----------------
// Output converted to fp16 and written to g_vimg[b][h][pix][dh].
__global__ __launch_bounds__(256) void gemm_val(
    const float* __restrict__ value, const float* __restrict__ W,
    const float* __restrict__ bias)
{
    __shared__ float As[BK_][ASTR_];
    __shared__ float Bs[BK_][64];
    const int tid = threadIdx.x;
    const int tx = tid & 15, ty = tid >> 4;
    const int row0 = blockIdx.y * 64;
    const int col0 = blockIdx.x * 64;
    const int bb = (row0 >= V_) ? 1 : 0;
    const int pix0 = row0 - bb * V_;
    const int a_m = tid >> 3, a_k = (tid & 7) << 2;
    const int b_k = tid >> 4, b_n = (tid & 15) << 2;
    const float* Arow0 = value + ((size_t)(pix0 + a_m) * BS_ + bb) * D_;
    const float* Arow1 = value + ((size_t)(pix0 + a_m + 32) * BS_ + bb) * D_;

    float acc[4][4] = {};
    for (int k0 = 0; k0 < 256; k0 += BK_) {
        float4 av0 = *reinterpret_cast<const float4*>(Arow0 + k0 + a_k);
        float4 av1 = *reinterpret_cast<const float4*>(Arow1 + k0 + a_k);
        As[a_k + 0][a_m] = av0.x;
        As[a_k + 1][a_m] = av0.y;
        As[a_k + 2][a_m] = av0.z;
        As[a_k + 3][a_m] = av0.w;
        As[a_k + 0][a_m + 32] = av1.x;
        As[a_k + 1][a_m + 32] = av1.y;
        As[a_k + 2][a_m + 32] = av1.z;
        As[a_k + 3][a_m + 32] = av1.w;
        *reinterpret_cast<float4*>(&Bs[b_k][b_n]) =
            *reinterpret_cast<const float4*>(&W[(size_t)(k0 + b_k) * 256 + col0 + b_n]);
        *reinterpret_cast<float4*>(&Bs[b_k + 16][b_n]) =
            *reinterpret_cast<const float4*>(&W[(size_t)(k0 + b_k + 16) * 256 + col0 + b_n]);
        __syncthreads();
        #pragma unroll
        for (int k = 0; k < BK_; k++) {
            float am[4], bn[4];
            #pragma unroll
            for (int i = 0; i < 4; i++) am[i] = As[k][ty * 4 + i];
            #pragma unroll
            for (int j = 0; j < 4; j++) bn[j] = Bs[k][tx * 4 + j];
            #pragma unroll
            for (int i = 0; i < 4; i++)
                #pragma unroll
                for (int j = 0; j < 4; j++) acc[i][j] += am[i] * bn[j];
        }
        __syncthreads();
    }
    const int col = col0 + tx * 4;           // 4 consecutive channels, same head
    const int h = col >> 5, dh = col & 31;
    float4 bv = *reinterpret_cast<const float4*>(&bias[col]);
    #pragma unroll
    for (int i = 0; i < 4; i++) {
        int pix = pix0 + ty * 4 + i;
        __half2 ha = __floats2half2_rn(acc[i][0] + bv.x, acc[i][1] + bv.y);
        __half2 hb = __floats2half2_rn(acc[i][2] + bv.z, acc[i][3] + bv.w);
        __half2* dst = reinterpret_cast<__half2*>(
            &g_vimg[(((size_t)(bb * NH_ + h)) * V_ + pix) * DH_ + dh]);
        dst[0] = ha;
        dst[1] = hb;
    }
}

// ---------------- softmax + sampling-coordinate precompute ----------------
__global__ __launch_bounds__(256) void coords_softmax(
    const float* __restrict__ trajs, const float* __restrict__ centers,
    float4* __restrict__ scw)
{
    int gid = blockIdx.x * blockDim.x + threadIdx.x;
    if (gid >= ROWS_ * NH_ * NS_) return;
    int r = gid / (NH_ * NS_);
    int rem = gid - r * (NH_ * NS_);
    int h = rem / NS_;
    int s = rem - h * NS_;
    int b = r / NQ_;
    int q = r - b * NQ_;
    int a = q / M_;
    const float* tr = trajs + ((size_t)(((b * A_ + a) * M_ + (q - a * M_)) * NS_ + (NS_ - 1))) * 2;
    float cx = centers[(b * A_ + a) * 2 + 0];
    float cy = centers[(b * A_ + a) * 2 + 1];
    const float sc = 200.0f / 102.4f;
    float xb = (tr[0] + cx + 51.2f) * sc - 0.5f;
    float yb = (tr[1] + cy + 51.2f) * sc - 0.5f;

    const float* awp  = g_aw  + (size_t)r * 384 + h * (NS_ * NP_) + s * NP_;
    const float* offp = g_off + (size_t)r * 768 + h * (NS_ * NP_ * 2) + s * (NP_ * 2);
    float a0 = awp[0], a1 = awp[1], a2 = awp[2], a3 = awp[3];
    float mx = fmaxf(fmaxf(a0, a1), fmaxf(a2, a3));
    float e0 = expf(a0 - mx), e1 = expf(a1 - mx), e2 = expf(a2 - mx), e3 = expf(a3 - mx);
    float inv = 1.0f / (e0 + e1 + e2 + e3);
    float w[4] = {e0 * inv, e1 * inv, e2 * inv, e3 * inv};

    float4* out = scw + (((size_t)r * NS_ + s) * NH_ + h) * NP_;
    #pragma unroll
    for (int p = 0; p < 4; p++)
        out[p] = make_float4(xb + offp[2 * p], yb + offp[2 * p + 1], w[p], 0.0f);
}

// ---------------- deformable sampling (fp16 image) ----------------
__global__ __launch_bounds__(256) void sample_kernel(
    const float4* __restrict__ scw, float* __restrict__ outp)
{
    const int blk = blockIdx.x;          // r*NS + s
    const int r = blk / NS_;
    const int s = blk - r * NS_;
    const int b = r / NQ_;
    __shared__ float4 sh[NH_ * NP_];
    const int t = threadIdx.x;
    if (t < NH_ * NP_) sh[t] = scw[(size_t)blk * (NH_ * NP_) + t];
    __syncthreads();

    const int h = t >> 5, dh = t & 31;
    const __half* img = g_vimg + (size_t)(b * NH_ + h) * V_ * DH_;
    float acc = 0.0f;
    #pragma unroll
    for (int p = 0; p < NP_; p++) {
        float4 s4 = sh[h * NP_ + p];
        float x = s4.x, y = s4.y, w = s4.z;
        float xf = floorf(x), yf = floorf(y);
        int x0 = (int)xf, y0 = (int)yf;
        float wx1 = x - xf, wy1 = y - yf;
        float wx0 = 1.0f - wx1, wy0 = 1.0f - wy1;
        bool xv0 = (x0 >= 0) & (x0 < WB_);
        bool xv1 = (x0 + 1 >= 0) & (x0 + 1 < WB_);
        bool yv0 = (y0 >= 0) & (y0 < HB_);
        bool yv1 = (y0 + 1 >= 0) & (y0 + 1 < HB_);
        float v00 = 0.f, v10 = 0.f, v01 = 0.f, v11 = 0.f;
        if (xv0 && yv0) v00 = __half2float(img[((size_t)(y0 * WB_ + x0)) * DH_ + dh]);
        if (xv1 && yv0) v10 = __half2float(img[((size_t)(y0 * WB_ + x0 + 1)) * DH_ + dh]);
        if (xv0 && yv1) v01 = __half2float(img[((size_t)((y0 + 1) * WB_ + x0)) * DH_ + dh]);
        if (xv1 && yv1) v11 = __half2float(img[((size_t)((y0 + 1) * WB_ + x0 + 1)) * DH_ + dh]);
        acc += w * (v00 * wx0 * wy0 + v10 * wx1 * wy0 + v01 * wx0 * wy1 + v11 * wx1 * wy1);
    }
    outp[(size_t)r * (NS_ * D_) + s * D_ + h * DH_ + dh] = acc;
}

// ---------------- LayerNorm + ReLU + residual (+ split-K reduction + bias) --------
__global__ __launch_bounds__(256) void ln_relu_res(
    const float* __restrict__ query, const float* __restrict__ bias,
    const float* __restrict__ gam, const float* __restrict__ bet,
    float* __restrict__ out)
{
    const int r = blockIdx.x;
    const int d = threadIdx.x;
    const size_t idx = (size_t)r * D_ + d;
    float v = g_opart[idx]
            + g_opart[(size_t)1 * ROWS_ * D_ + idx]
            + g_opart[(size_t)2 * ROWS_ * D_ + idx]
            + g_opart[(size_t)3 * ROWS_ * D_ + idx]
            + bias[d];
    float s1 = v, s2 = v * v;
    __shared__ float shs[8], shq[8];
    const int lane = d & 31, w = d >> 5;
    #pragma unroll
    for (int o = 16; o; o >>= 1) {
        s1 += __shfl_xor_sync(0xffffffffu, s1, o);
        s2 += __shfl_xor_sync(0xffffffffu, s2, o);
    }
    if (lane == 0) { shs[w] = s1; shq[w] = s2; }
    __syncthreads();
    if (d == 0) {
        float t1 = 0.f, t2 = 0.f;
        #pragma unroll
        for (int i = 0; i < 8; i++) { t1 += shs[i]; t2 += shq[i]; }
        shs[0] = t1 * (1.0f / D_);
        shq[0] = t2 * (1.0f / D_);
    }
    __syncthreads();
    float mu = shs[0];
    float var = shq[0] - mu * mu;
    float y = (v - mu) * rsqrtf(var + LN_EPS) * gam[d] + bet[d];
    y = fmaxf(y, 0.0f);
    out[idx] = y + query[idx];
}

// ---------------- launch ----------------
extern "C" void kernel_launch(void* const* d_in, const int* in_sizes, int n_in,
                              void* d_out, int out_size)
{
    const float* query      = (const float*)d_in[0];
    const float* query_pos  = (const float*)d_in[1];
    const float* value      = (const float*)d_in[2];
    const float* ref_trajs  = (const float*)d_in[3];
    const float* centers    = (const float*)d_in[4];
    const float* W_off      = (const float*)d_in[5];
    const float* b_off      = (const float*)d_in[6];
    const float* W_attn     = (const float*)d_in[7];
    const float* b_attn     = (const float*)d_in[8];
    const float* W_val      = (const float*)d_in[9];
    const float* b_val      = (const float*)d_in[10];
    const float* W_out      = (const float*)d_in[11];
    const float* b_out      = (const float*)d_in[12];
    const float* ln_g       = (const float*)d_in[13];
    const float* ln_b       = (const float*)d_in[14];
    float* out = (float*)d_out;

    float *offb, *awb, *samp;
    float4* scw;
    cudaGetSymbolAddress((void**)&offb, g_off);
    cudaGetSymbolAddress((void**)&awb,  g_aw);
    cudaGetSymbolAddress((void**)&scw,  g_scw);
    cudaGetSymbolAddress((void**)&samp, g_samp);

    // 1) value projection + fp16 layout transform: (80000x256)@(256x256) -> g_vimg
    gemm_val<<<dim3(4, (BS_ * V_) / 64), 256>>>(value, W_val, b_val);

    // 2) offset + attention projections: (3072x256)@(256x768 / 256x384)
    sgemm_bias<<<dim3(768 / 64, ROWS_ / 64), 256>>>(query, query_pos, W_off, b_off, offb, ROWS_, 768, 256);
    sgemm_bias<<<dim3(384 / 64, ROWS_ / 64), 256>>>(query, query_pos, W_attn, b_attn, awb, ROWS_, 384, 256);

    // 3) softmax + sampling coordinates
    coords_softmax<<<(ROWS_ * NH_ * NS_ + 255) / 256, 256>>>(ref_trajs, centers, scw);

    // 4) bilinear gather + attention-weighted sum (fp16 image)
    sample_kernel<<<ROWS_ * NS_, 256>>>(scw, samp);

    // 5) output projection, split-K x4: (3072x3072)@(3072x256) -> 4 partials
    gemm_out_splitk<<<dim3(D_ / 64, ROWS_ / 64, KSPLIT), 256>>>(W_out);

    // 6) split-K reduce + bias + LayerNorm + ReLU + residual
    ln_relu_res<<<ROWS_, 256>>>(query, b_out, ln_g, ln_b, out);
}

// round 14
// speedup vs baseline: 1.0772x; 1.0772x over previous
#include <cuda_runtime.h>
#include <mma.h>

using namespace nvcuda;

// ---------------- problem constants ----------------
#define D_     256
#define NH_    8
#define DH_    32
#define NS_    12
#define NP_    4
#define HB_    200
#define WB_    200
#define V_     (HB_*WB_)       // 40000
#define BS_    2
#define A_     256
#define M_     6
#define NQ_    (A_*M_)         // 1536
#define ROWS_  (BS_*NQ_)       // 3072
#define LN_EPS 1e-5f

#define BK_    32
#define ASTR_  68
#define KSPLIT 4               // split-K factor for the out-projection GEMM

// ---------------- device scratch (static, allocation-free) ----------------
__device__ __align__(16) float g_vimg[(size_t)BS_*NH_*V_*DH_];     // [b][h][pix][dh]
__device__ __align__(16) float g_off [(size_t)ROWS_*768];
__device__ __align__(16) float g_aw  [(size_t)ROWS_*384];
__device__ __align__(16) float4 g_scw[(size_t)ROWS_*NS_*NH_*NP_];  // (x, y, weight, pad)
__device__ __align__(16) float g_samp[(size_t)ROWS_*NS_*D_];       // (3072, 3072)
__device__ __align__(16) float g_opart[(size_t)KSPLIT*ROWS_*D_];   // split-K partials

// ---------------- generic SGEMM (SIMT, unchanged): C = (A [+Aadd]) @ B + bias ----
__global__ __launch_bounds__(256) void sgemm_bias(
    const float* __restrict__ A, const float* __restrict__ Aadd,
    const float* __restrict__ B, const float* __restrict__ bias,
    float* __restrict__ C, int M, int N, int K)
{
    __shared__ float As[BK_][ASTR_];
    __shared__ float Bs[BK_][64];
    const int tid = threadIdx.x;
    const int tx = tid & 15, ty = tid >> 4;
    const int row0 = blockIdx.y * 64;
    const int col0 = blockIdx.x * 64;
    const int a_m = tid >> 3, a_k = (tid & 7) << 2;
    const int b_k = tid >> 4, b_n = (tid & 15) << 2;

    float acc[4][4] = {};
    for (int k0 = 0; k0 < K; k0 += BK_) {
        float4 av0 = *reinterpret_cast<const float4*>(&A[(size_t)(row0 + a_m) * K + k0 + a_k]);
        float4 av1 = *reinterpret_cast<const float4*>(&A[(size_t)(row0 + a_m + 32) * K + k0 + a_k]);
        if (Aadd) {
            float4 p0 = *reinterpret_cast<const float4*>(&Aadd[(size_t)(row0 + a_m) * K + k0 + a_k]);
            av0.x += p0.x; av0.y += p0.y; av0.z += p0.z; av0.w += p0.w;
            float4 p1 = *reinterpret_cast<const float4*>(&Aadd[(size_t)(row0 + a_m + 32) * K + k0 + a_k]);
            av1.x += p1.x; av1.y += p1.y; av1.z += p1.z; av1.w += p1.w;
        }
        As[a_k + 0][a_m] = av0.x;
        As[a_k + 1][a_m] = av0.y;
        As[a_k + 2][a_m] = av0.z;
        As[a_k + 3][a_m] = av0.w;
        As[a_k + 0][a_m + 32] = av1.x;
        As[a_k + 1][a_m + 32] = av1.y;
        As[a_k + 2][a_m + 32] = av1.z;
        As[a_k + 3][a_m + 32] = av1.w;
        *reinterpret_cast<float4*>(&Bs[b_k][b_n]) =
            *reinterpret_cast<const float4*>(&B[(size_t)(k0 + b_k) * N + col0 + b_n]);
        *reinterpret_cast<float4*>(&Bs[b_k + 16][b_n]) =
            *reinterpret_cast<const float4*>(&B[(size_t)(k0 + b_k + 16) * N + col0 + b_n]);
        __syncthreads();
        #pragma unroll
        for (int k = 0; k < BK_; k++) {
            float am[4], bn[4];
            #pragma unroll
            for (int i = 0; i < 4; i++) am[i] = As[k][ty * 4 + i];
            #pragma unroll
            for (int j = 0; j < 4; j++) bn[j] = Bs[k][tx * 4 + j];
            #pragma unroll
            for (int i = 0; i < 4; i++)
                #pragma unroll
                for (int j = 0; j < 4; j++) acc[i][j] += am[i] * bn[j];
        }
        __syncthreads();
    }
    const int col = col0 + tx * 4;
    float4 bv = *reinterpret_cast<const float4*>(&bias[col]);
    #pragma unroll
    for (int i = 0; i < 4; i++) {
        int row = row0 + ty * 4 + i;
        float4 o = make_float4(acc[i][0] + bv.x, acc[i][1] + bv.y,
                               acc[i][2] + bv.z, acc[i][3] + bv.w);
        *reinterpret_cast<float4*>(&C[(size_t)row * N + col]) = o;
    }
}

// ---------------- tf32 wmma value-projection GEMM (lean: 2 acc frags/thread) ----
// 64x64 tile, 8 warps: warp w -> rows (w>>1)*16, cols (w&1)*32 (+nt*16).
// Bias pre-loaded into accumulators; store_matrix_sync scatters directly into
// g_vimg[b][h][pix][dh] (16-col warp tiles stay within one head: col%32 in {0,16}).
__global__ __launch_bounds__(256) void gemm_val_wmma(
    const float* __restrict__ value, const float* __restrict__ W,
    const float* __restrict__ bias)
{
    __shared__ float As[64][20];   // [m][k], tf32 bits
    __shared__ float Bs[16][68];   // [k][n], tf32 bits (also bias staging)

    const int tid  = threadIdx.x;
    const int warp = tid >> 5;
    const int wm = warp >> 1;          // 0..3
    const int wn = warp & 1;           // 0..1

    const int row0 = blockIdx.y * 64;
    const int col0 = blockIdx.x * 64;
    const int bb = (row0 >= V_) ? 1 : 0;
    const int pix0 = row0 - bb * V_;

    const int a_row = tid >> 2, a_kc = (tid & 3) << 2;   // A: 64x16, 1 float4/thread
    const int b_row = tid >> 4, b_nc = (tid & 15) << 2;  // B: 16x64, 1 float4/thread
    const size_t a_base = ((size_t)(pix0 + a_row) * BS_ + bb) * 256;

    wmma::fragment<wmma::accumulator, 16, 16, 8, float> acc[2];

    // ---- init accumulators with bias (replicated rows in Bs) ----
    {
        float4 bv = *reinterpret_cast<const float4*>(&bias[col0 + b_nc]);
        Bs[b_row][b_nc + 0] = bv.x;
        Bs[b_row][b_nc + 1] = bv.y;
        Bs[b_row][b_nc + 2] = bv.z;
        Bs[b_row][b_nc + 3] = bv.w;
        __syncthreads();
        wmma::load_matrix_sync(acc[0], &Bs[0][wn * 32], 68, wmma::mem_row_major);
        wmma::load_matrix_sync(acc[1], &Bs[0][wn * 32 + 16], 68, wmma::mem_row_major);
        __syncthreads();
    }

    for (int k0 = 0; k0 < 256; k0 += 16) {
        float4 av = *reinterpret_cast<const float4*>(&value[a_base + k0 + a_kc]);
        As[a_row][a_kc + 0] = wmma::__float_to_tf32(av.x);
        As[a_row][a_kc + 1] = wmma::__float_to_tf32(av.y);
        As[a_row][a_kc + 2] = wmma::__float_to_tf32(av.z);
        As[a_row][a_kc + 3] = wmma::__float_to_tf32(av.w);
        float4 bv = *reinterpret_cast<const float4*>(&W[(size_t)(k0 + b_row) * 256 + col0 + b_nc]);
        Bs[b_row][b_nc + 0] = wmma::__float_to_tf32(bv.x);
        Bs[b_row][b_nc + 1] = wmma::__float_to_tf32(bv.y);
        Bs[b_row][b_nc + 2] = wmma::__float_to_tf32(bv.z);
        Bs[b_row][b_nc + 3] = wmma::__float_to_tf32(bv.w);
        __syncthreads();

        #pragma unroll
        for (int ks = 0; ks < 16; ks += 8) {
            wmma::fragment<wmma::matrix_a, 16, 16, 8, wmma::precision::tf32, wmma::row_major> af;
            wmma::fragment<wmma::matrix_b, 16, 16, 8, wmma::precision::tf32, wmma::row_major> bf;
            wmma::load_matrix_sync(af, &As[wm * 16][ks], 20);
            wmma::load_matrix_sync(bf, &Bs[ks][wn * 32], 68);
            wmma::mma_sync(acc[0], af, bf, acc[0]);
            wmma::load_matrix_sync(bf, &Bs[ks][wn * 32 + 16], 68);
            wmma::mma_sync(acc[1], af, bf, acc[1]);
        }
        __syncthreads();
    }

    // ---- direct scattered store: cols col0+wn*32+nt*16 -> head h, dh = nt*16 ----
    const int gc = col0 + wn * 32;         // multiple of 32 -> dh0 = 0
    const int h = gc >> 5;
    float* base = &g_vimg[(((size_t)(bb * NH_ + h)) * V_ + (pix0 + wm * 16)) * DH_];
    wmma::store_matrix_sync(base, acc[0], DH_, wmma::mem_row_major);
    wmma::store_matrix_sync(base + 16, acc[1], DH_, wmma::mem_row_major);
}

// ---------------- tf32 wmma split-K out-projection ----------------
// partial[z] = g_samp[:, z*768:+768] @ W_out[z*768:, :]; no bias (folded in LN).
__global__ __launch_bounds__(256) void gemm_out_splitk_wmma(
    const float* __restrict__ B)
{
    __shared__ float As[64][20];
    __shared__ float Bs[16][68];

    const int tid  = threadIdx.x;
    const int warp = tid >> 5;
    const int wm = warp >> 1;
    const int wn = warp & 1;

    const int row0 = blockIdx.y * 64;
    const int col0 = blockIdx.x * 64;
    const int slice = blockIdx.z;
    const int kbase = slice * (3072 / KSPLIT);

    const int a_row = tid >> 2, a_kc = (tid & 3) << 2;
    const int b_row = tid >> 4, b_nc = (tid & 15) << 2;
    float* __restrict__ C = g_opart + (size_t)slice * ROWS_ * D_;

    wmma::fragment<wmma::accumulator, 16, 16, 8, float> acc[2];
    wmma::fill_fragment(acc[0], 0.0f);
    wmma::fill_fragment(acc[1], 0.0f);

    for (int kk = 0; kk < 3072 / KSPLIT; kk += 16) {
        const int k0 = kbase + kk;
        float4 av = *reinterpret_cast<const float4*>(
            &g_samp[(size_t)(row0 + a_row) * 3072 + k0 + a_kc]);
        As[a_row][a_kc + 0] = wmma::__float_to_tf32(av.x);
        As[a_row][a_kc + 1] = wmma::__float_to_tf32(av.y);
        As[a_row][a_kc + 2] = wmma::__float_to_tf32(av.z);
        As[a_row][a_kc + 3] = wmma::__float_to_tf32(av.w);
        float4 bv = *reinterpret_cast<const float4*>(&B[(size_t)(k0 + b_row) * 256 + col0 + b_nc]);
        Bs[b_row][b_nc + 0] = wmma::__float_to_tf32(bv.x);
        Bs[b_row][b_nc + 1] = wmma::__float_to_tf32(bv.y);
        Bs[b_row][b_nc + 2] = wmma::__float_to_tf32(bv.z);
        Bs[b_row][b_nc + 3] = wmma::__float_to_tf32(bv.w);
        __syncthreads();

        #pragma unroll
        for (int ks = 0; ks < 16; ks += 8) {
            wmma::fragment<wmma::matrix_a, 16, 16, 8, wmma::precision::tf32, wmma::row_major> af;
            wmma::fragment<wmma::matrix_b, 16, 16, 8, wmma::precision::tf32, wmma::row_major> bf;
            wmma::load_matrix_sync(af, &As[wm * 16][ks], 20);
            wmma::load_matrix_sync(bf, &Bs[ks][wn * 32], 68);
            wmma::mma_sync(acc[0], af, bf, acc[0]);
            wmma::load_matrix_sync(bf, &Bs[ks][wn * 32 + 16], 68);
            wmma::mma_sync(acc[1], af, bf, acc[1]);
        }
        __syncthreads();
    }

    float* base = &C[(size_t)(row0 + wm * 16) * D_ + col0 + wn * 32];
    wmma::store_matrix_sync(base, acc[0], D_, wmma::mem_row_major);
    wmma::store_matrix_sync(base + 16, acc[1], D_, wmma::mem_row_major);
}

// ---------------- softmax + sampling-coordinate precompute ----------------
__global__ __launch_bounds__(256) void coords_softmax(
    const float* __restrict__ trajs, const float* __restrict__ centers,
    float4* __restrict__ scw)
{
    int gid = blockIdx.x * blockDim.x + threadIdx.x;
    if (gid >= ROWS_ * NH_ * NS_) return;
    int r = gid / (NH_ * NS_);
    int rem = gid - r * (NH_ * NS_);
    int h = rem / NS_;
    int s = rem - h * NS_;
    int b = r / NQ_;
    int q = r - b * NQ_;
    int a = q / M_;
    const float* tr = trajs + ((size_t)(((b * A_ + a) * M_ + (q - a * M_)) * NS_ + (NS_ - 1))) * 2;
    float cx = centers[(b * A_ + a) * 2 + 0];
    float cy = centers[(b * A_ + a) * 2 + 1];
    const float sc = 200.0f / 102.4f;
    float xb = (tr[0] + cx + 51.2f) * sc - 0.5f;
    float yb = (tr[1] + cy + 51.2f) * sc - 0.5f;

    const float* awp  = g_aw  + (size_t)r * 384 + h * (NS_ * NP_) + s * NP_;
    const float* offp = g_off + (size_t)r * 768 + h * (NS_ * NP_ * 2) + s * (NP_ * 2);
    float a0 = awp[0], a1 = awp[1], a2 = awp[2], a3 = awp[3];
    float mx = fmaxf(fmaxf(a0, a1), fmaxf(a2, a3));
    float e0 = expf(a0 - mx), e1 = expf(a1 - mx), e2 = expf(a2 - mx), e3 = expf(a3 - mx);
    float inv = 1.0f / (e0 + e1 + e2 + e3);
    float w[4] = {e0 * inv, e1 * inv, e2 * inv, e3 * inv};

    float4* out = scw + (((size_t)r * NS_ + s) * NH_ + h) * NP_;
    #pragma unroll
    for (int p = 0; p < 4; p++)
        out[p] = make_float4(xb + offp[2 * p], yb + offp[2 * p + 1], w[p], 0.0f);
}

// ---------------- deformable sampling (fp32 image) ----------------
__global__ __launch_bounds__(256) void sample_kernel(
    const float4* __restrict__ scw, float* __restrict__ outp)
{
    const int blk = blockIdx.x;          // r*NS + s
    const int r = blk / NS_;
    const int s = blk - r * NS_;
    const int b = r / NQ_;
    __shared__ float4 sh[NH_ * NP_];
    const int t = threadIdx.x;
    if (t < NH_ * NP_) sh[t] = scw[(size_t)blk * (NH_ * NP_) + t];
    __syncthreads();

    const int h = t >> 5, dh = t & 31;
    const float* img = g_vimg + (size_t)(b * NH_ + h) * V_ * DH_;
    float acc = 0.0f;
    #pragma unroll
    for (int p = 0; p < NP_; p++) {
        float4 s4 = sh[h * NP_ + p];
        float x = s4.x, y = s4.y, w = s4.z;
        float xf = floorf(x), yf = floorf(y);
        int x0 = (int)xf, y0 = (int)yf;
        float wx1 = x - xf, wy1 = y - yf;
        float wx0 = 1.0f - wx1, wy0 = 1.0f - wy1;
        bool xv0 = (x0 >= 0) & (x0 < WB_);
        bool xv1 = (x0 + 1 >= 0) & (x0 + 1 < WB_);
        bool yv0 = (y0 >= 0) & (y0 < HB_);
        bool yv1 = (y0 + 1 >= 0) & (y0 + 1 < HB_);
        float v00 = 0.f, v10 = 0.f, v01 = 0.f, v11 = 0.f;
        if (xv0 && yv0) v00 = img[((size_t)(y0 * WB_ + x0)) * DH_ + dh];
        if (xv1 && yv0) v10 = img[((size_t)(y0 * WB_ + x0 + 1)) * DH_ + dh];
        if (xv0 && yv1) v01 = img[((size_t)((y0 + 1) * WB_ + x0)) * DH_ + dh];
        if (xv1 && yv1) v11 = img[((size_t)((y0 + 1) * WB_ + x0 + 1)) * DH_ + dh];
        acc += w * (v00 * wx0 * wy0 + v10 * wx1 * wy0 + v01 * wx0 * wy1 + v11 * wx1 * wy1);
    }
    outp[(size_t)r * (NS_ * D_) + s * D_ + h * DH_ + dh] = acc;
}

// ---------------- LayerNorm + ReLU + residual (+ split-K reduction + bias) --------
__global__ __launch_bounds__(256) void ln_relu_res(
    const float* __restrict__ query, const float* __restrict__ bias,
    const float* __restrict__ gam, const float* __restrict__ bet,
    float* __restrict__ out)
{
    const int r = blockIdx.x;
    const int d = threadIdx.x;
    const size_t idx = (size_t)r * D_ + d;
    float v = g_opart[idx]
            + g_opart[(size_t)1 * ROWS_ * D_ + idx]
            + g_opart[(size_t)2 * ROWS_ * D_ + idx]
            + g_opart[(size_t)3 * ROWS_ * D_ + idx]
            + bias[d];
    float s1 = v, s2 = v * v;
    __shared__ float shs[8], shq[8];
    const int lane = d & 31, w = d >> 5;
    #pragma unroll
    for (int o = 16; o; o >>= 1) {
        s1 += __shfl_xor_sync(0xffffffffu, s1, o);
        s2 += __shfl_xor_sync(0xffffffffu, s2, o);
    }
    if (lane == 0) { shs[w] = s1; shq[w] = s2; }
    __syncthreads();
    if (d == 0) {
        float t1 = 0.f, t2 = 0.f;
        #pragma unroll
        for (int i = 0; i < 8; i++) { t1 += shs[i]; t2 += shq[i]; }
        shs[0] = t1 * (1.0f / D_);
        shq[0] = t2 * (1.0f / D_);
    }
    __syncthreads();
    float mu = shs[0];
    float var = shq[0] - mu * mu;
    float y = (v - mu) * rsqrtf(var + LN_EPS) * gam[d] + bet[d];
    y = fmaxf(y, 0.0f);
    out[idx] = y + query[idx];
}

// ---------------- launch ----------------
extern "C" void kernel_launch(void* const* d_in, const int* in_sizes, int n_in,
                              void* d_out, int out_size)
{
    const float* query      = (const float*)d_in[0];
    const float* query_pos  = (const float*)d_in[1];
    const float* value      = (const float*)d_in[2];
    const float* ref_trajs  = (const float*)d_in[3];
    const float* centers    = (const float*)d_in[4];
    const float* W_off      = (const float*)d_in[5];
    const float* b_off      = (const float*)d_in[6];
    const float* W_attn     = (const float*)d_in[7];
    const float* b_attn     = (const float*)d_in[8];
    const float* W_val      = (const float*)d_in[9];
    const float* b_val      = (const float*)d_in[10];
    const float* W_out      = (const float*)d_in[11];
    const float* b_out      = (const float*)d_in[12];
    const float* ln_g       = (const float*)d_in[13];
    const float* ln_b       = (const float*)d_in[14];
    float* out = (float*)d_out;

    float *offb, *awb, *samp;
    float4* scw;
    cudaGetSymbolAddress((void**)&offb, g_off);
    cudaGetSymbolAddress((void**)&awb,  g_aw);
    cudaGetSymbolAddress((void**)&scw,  g_scw);
    cudaGetSymbolAddress((void**)&samp, g_samp);

    // 1) value projection + layout transform (tf32 wmma): -> g_vimg
    gemm_val_wmma<<<dim3(4, (BS_ * V_) / 64), 256>>>(value, W_val, b_val);

    // 2) offset + attention projections (fp32 SIMT, unchanged)
    sgemm_bias<<<dim3(768 / 64, ROWS_ / 64), 256>>>(query, query_pos, W_off, b_off, offb, ROWS_, 768, 256);
    sgemm_bias<<<dim3(384 / 64, ROWS_ / 64), 256>>>(query, query_pos, W_attn, b_attn, awb, ROWS_, 384, 256);

    // 3) softmax + sampling coordinates
    coords_softmax<<<(ROWS_ * NH_ * NS_ + 255) / 256, 256>>>(ref_trajs, centers, scw);

    // 4) bilinear gather + attention-weighted sum
    sample_kernel<<<ROWS_ * NS_, 256>>>(scw, samp);

    // 5) output projection, split-K x4 (tf32 wmma)
    gemm_out_splitk_wmma<<<dim3(D_ / 64, ROWS_ / 64, KSPLIT), 256>>>(W_out);

    // 6) split-K reduce + bias + LayerNorm + ReLU + residual
    ln_relu_res<<<ROWS_, 256>>>(query, b_out, ln_g, ln_b, out);
}

// round 15
// speedup vs baseline: 1.2513x; 1.1616x over previous
#include <cuda_runtime.h>
#include <mma.h>

using namespace nvcuda;

// ---------------- problem constants ----------------
#define D_     256
#define NH_    8
#define DH_    32
#define NS_    12
#define NP_    4
#define HB_    200
#define WB_    200
#define V_     (HB_*WB_)       // 40000
#define BS_    2
#define A_     256
#define M_     6
#define NQ_    (A_*M_)         // 1536
#define ROWS_  (BS_*NQ_)       // 3072
#define LN_EPS 1e-5f

#define BK_    32
#define ASTR_  68
#define KSPLIT 4               // split-K factor for the out-projection GEMM

// ---------------- device scratch (static, allocation-free) ----------------
__device__ __align__(16) float g_vimg[(size_t)BS_*NH_*V_*DH_];     // [b][h][pix][dh]
__device__ __align__(16) float g_off [(size_t)ROWS_*768];
__device__ __align__(16) float g_aw  [(size_t)ROWS_*384];
__device__ __align__(16) float4 g_scw[(size_t)ROWS_*NS_*NH_*NP_];  // (x, y, weight, pad)
__device__ __align__(16) float g_samp[(size_t)ROWS_*NS_*D_];       // (3072, 3072)
__device__ __align__(16) float g_opart[(size_t)KSPLIT*ROWS_*D_];   // split-K partials

// ---------------- generic SGEMM (SIMT, unchanged): C = (A [+Aadd]) @ B + bias ----
__global__ __launch_bounds__(256) void sgemm_bias(
    const float* __restrict__ A, const float* __restrict__ Aadd,
    const float* __restrict__ B, const float* __restrict__ bias,
    float* __restrict__ C, int M, int N, int K)
{
    __shared__ float As[BK_][ASTR_];
    __shared__ float Bs[BK_][64];
    const int tid = threadIdx.x;
    const int tx = tid & 15, ty = tid >> 4;
    const int row0 = blockIdx.y * 64;
    const int col0 = blockIdx.x * 64;
    const int a_m = tid >> 3, a_k = (tid & 7) << 2;
    const int b_k = tid >> 4, b_n = (tid & 15) << 2;

    float acc[4][4] = {};
    for (int k0 = 0; k0 < K; k0 += BK_) {
        float4 av0 = *reinterpret_cast<const float4*>(&A[(size_t)(row0 + a_m) * K + k0 + a_k]);
        float4 av1 = *reinterpret_cast<const float4*>(&A[(size_t)(row0 + a_m + 32) * K + k0 + a_k]);
        if (Aadd) {
            float4 p0 = *reinterpret_cast<const float4*>(&Aadd[(size_t)(row0 + a_m) * K + k0 + a_k]);
            av0.x += p0.x; av0.y += p0.y; av0.z += p0.z; av0.w += p0.w;
            float4 p1 = *reinterpret_cast<const float4*>(&Aadd[(size_t)(row0 + a_m + 32) * K + k0 + a_k]);
            av1.x += p1.x; av1.y += p1.y; av1.z += p1.z; av1.w += p1.w;
        }
        As[a_k + 0][a_m] = av0.x;
        As[a_k + 1][a_m] = av0.y;
        As[a_k + 2][a_m] = av0.z;
        As[a_k + 3][a_m] = av0.w;
        As[a_k + 0][a_m + 32] = av1.x;
        As[a_k + 1][a_m + 32] = av1.y;
        As[a_k + 2][a_m + 32] = av1.z;
        As[a_k + 3][a_m + 32] = av1.w;
        *reinterpret_cast<float4*>(&Bs[b_k][b_n]) =
            *reinterpret_cast<const float4*>(&B[(size_t)(k0 + b_k) * N + col0 + b_n]);
        *reinterpret_cast<float4*>(&Bs[b_k + 16][b_n]) =
            *reinterpret_cast<const float4*>(&B[(size_t)(k0 + b_k + 16) * N + col0 + b_n]);
        __syncthreads();
        #pragma unroll
        for (int k = 0; k < BK_; k++) {
            float am[4], bn[4];
            #pragma unroll
            for (int i = 0; i < 4; i++) am[i] = As[k][ty * 4 + i];
            #pragma unroll
            for (int j = 0; j < 4; j++) bn[j] = Bs[k][tx * 4 + j];
            #pragma unroll
            for (int i = 0; i < 4; i++)
                #pragma unroll
                for (int j = 0; j < 4; j++) acc[i][j] += am[i] * bn[j];
        }
        __syncthreads();
    }
    const int col = col0 + tx * 4;
    float4 bv = *reinterpret_cast<const float4*>(&bias[col]);
    #pragma unroll
    for (int i = 0; i < 4; i++) {
        int row = row0 + ty * 4 + i;
        float4 o = make_float4(acc[i][0] + bv.x, acc[i][1] + bv.y,
                               acc[i][2] + bv.z, acc[i][3] + bv.w);
        *reinterpret_cast<float4*>(&C[(size_t)row * N + col]) = o;
    }
}

// ---------------- tf32 wmma value-projection GEMM: 128x64 tile, 4 acc frags/warp ----
// 8 warps, warp w -> row band w*16 (all 64 cols). A rows decode (b,pix) per row
// (boundary tile straddles b at pix 40000); 16-row bands never straddle (40000%16==0).
// Bias pre-loaded into accumulators; direct scattered store into g_vimg.
__global__ __launch_bounds__(256) void gemm_val_wmma(
    const float* __restrict__ value, const float* __restrict__ W,
    const float* __restrict__ bias)
{
    __shared__ float As[128][20];  // [m][k] tf32 bits
    __shared__ float Bs[16][68];   // [k][n] tf32 bits (also bias staging)

    const int tid  = threadIdx.x;
    const int wm   = tid >> 5;         // 0..7 -> row band

    const int row0 = blockIdx.y * 128;
    const int col0 = blockIdx.x * 64;

    // A: 128x16 = 2 float4/thread (rows tid>>2 and +64); per-row batch decode
    const int a_row0 = tid >> 2, a_kc = (tid & 3) << 2;
    const int a_row1 = a_row0 + 64;
    size_t a_base0, a_base1;
    {
        int g0 = row0 + a_row0, g1 = row0 + a_row1;
        int bb0 = (g0 >= V_) ? 1 : 0, bb1 = (g1 >= V_) ? 1 : 0;
        a_base0 = ((size_t)(g0 - bb0 * V_) * BS_ + bb0) * 256;
        a_base1 = ((size_t)(g1 - bb1 * V_) * BS_ + bb1) * 256;
    }
    const int b_row = tid >> 4, b_nc = (tid & 15) << 2;  // B: 16x64, 1 float4/thread

    wmma::fragment<wmma::accumulator, 16, 16, 8, float> acc[4];

    // ---- init accumulators with bias (replicated rows in Bs) ----
    {
        float4 bv = *reinterpret_cast<const float4*>(&bias[col0 + b_nc]);
        Bs[b_row][b_nc + 0] = bv.x;
        Bs[b_row][b_nc + 1] = bv.y;
        Bs[b_row][b_nc + 2] = bv.z;
        Bs[b_row][b_nc + 3] = bv.w;
        __syncthreads();
        #pragma unroll
        for (int nf = 0; nf < 4; nf++)
            wmma::load_matrix_sync(acc[nf], &Bs[0][nf * 16], 68, wmma::mem_row_major);
        __syncthreads();
    }

    for (int k0 = 0; k0 < 256; k0 += 16) {
        float4 av0 = *reinterpret_cast<const float4*>(&value[a_base0 + k0 + a_kc]);
        float4 av1 = *reinterpret_cast<const float4*>(&value[a_base1 + k0 + a_kc]);
        As[a_row0][a_kc + 0] = wmma::__float_to_tf32(av0.x);
        As[a_row0][a_kc + 1] = wmma::__float_to_tf32(av0.y);
        As[a_row0][a_kc + 2] = wmma::__float_to_tf32(av0.z);
        As[a_row0][a_kc + 3] = wmma::__float_to_tf32(av0.w);
        As[a_row1][a_kc + 0] = wmma::__float_to_tf32(av1.x);
        As[a_row1][a_kc + 1] = wmma::__float_to_tf32(av1.y);
        As[a_row1][a_kc + 2] = wmma::__float_to_tf32(av1.z);
        As[a_row1][a_kc + 3] = wmma::__float_to_tf32(av1.w);
        float4 bv = *reinterpret_cast<const float4*>(&W[(size_t)(k0 + b_row) * 256 + col0 + b_nc]);
        Bs[b_row][b_nc + 0] = wmma::__float_to_tf32(bv.x);
        Bs[b_row][b_nc + 1] = wmma::__float_to_tf32(bv.y);
        Bs[b_row][b_nc + 2] = wmma::__float_to_tf32(bv.z);
        Bs[b_row][b_nc + 3] = wmma::__float_to_tf32(bv.w);
        __syncthreads();

        #pragma unroll
        for (int ks = 0; ks < 16; ks += 8) {
            wmma::fragment<wmma::matrix_a, 16, 16, 8, wmma::precision::tf32, wmma::row_major> af;
            wmma::load_matrix_sync(af, &As[wm * 16][ks], 20);
            #pragma unroll
            for (int nf = 0; nf < 4; nf++) {
                wmma::fragment<wmma::matrix_b, 16, 16, 8, wmma::precision::tf32, wmma::row_major> bf;
                wmma::load_matrix_sync(bf, &Bs[ks][nf * 16], 68);
                wmma::mma_sync(acc[nf], af, bf, acc[nf]);
            }
        }
        __syncthreads();
    }

    // ---- direct scattered store: band gr..gr+15 in one batch; 16-col frags in one head ----
    const int gr = row0 + wm * 16;
    const int bb = (gr >= V_) ? 1 : 0;
    const int pix = gr - bb * V_;
    #pragma unroll
    for (int nf = 0; nf < 4; nf++) {
        const int gc = col0 + nf * 16;
        const int h = gc >> 5, dh = gc & 31;   // dh in {0,16}
        float* base = &g_vimg[(((size_t)(bb * NH_ + h)) * V_ + pix) * DH_ + dh];
        wmma::store_matrix_sync(base, acc[nf], DH_, wmma::mem_row_major);
    }
}

// ---------------- tf32 wmma split-K out-projection: 128x64 tile, 4 frags/warp ----
__global__ __launch_bounds__(256) void gemm_out_splitk_wmma(
    const float* __restrict__ B)
{
    __shared__ float As[128][20];
    __shared__ float Bs[16][68];

    const int tid = threadIdx.x;
    const int wm  = tid >> 5;          // 0..7

    const int row0 = blockIdx.y * 128;
    const int col0 = blockIdx.x * 64;
    const int slice = blockIdx.z;
    const int kbase = slice * (3072 / KSPLIT);

    const int a_row0 = tid >> 2, a_kc = (tid & 3) << 2;
    const int a_row1 = a_row0 + 64;
    const int b_row = tid >> 4, b_nc = (tid & 15) << 2;
    float* __restrict__ C = g_opart + (size_t)slice * ROWS_ * D_;

    wmma::fragment<wmma::accumulator, 16, 16, 8, float> acc[4];
    #pragma unroll
    for (int nf = 0; nf < 4; nf++) wmma::fill_fragment(acc[nf], 0.0f);

    for (int kk = 0; kk < 3072 / KSPLIT; kk += 16) {
        const int k0 = kbase + kk;
        float4 av0 = *reinterpret_cast<const float4*>(
            &g_samp[(size_t)(row0 + a_row0) * 3072 + k0 + a_kc]);
        float4 av1 = *reinterpret_cast<const float4*>(
            &g_samp[(size_t)(row0 + a_row1) * 3072 + k0 + a_kc]);
        As[a_row0][a_kc + 0] = wmma::__float_to_tf32(av0.x);
        As[a_row0][a_kc + 1] = wmma::__float_to_tf32(av0.y);
        As[a_row0][a_kc + 2] = wmma::__float_to_tf32(av0.z);
        As[a_row0][a_kc + 3] = wmma::__float_to_tf32(av0.w);
        As[a_row1][a_kc + 0] = wmma::__float_to_tf32(av1.x);
        As[a_row1][a_kc + 1] = wmma::__float_to_tf32(av1.y);
        As[a_row1][a_kc + 2] = wmma::__float_to_tf32(av1.z);
        As[a_row1][a_kc + 3] = wmma::__float_to_tf32(av1.w);
        float4 bv = *reinterpret_cast<const float4*>(&B[(size_t)(k0 + b_row) * 256 + col0 + b_nc]);
        Bs[b_row][b_nc + 0] = wmma::__float_to_tf32(bv.x);
        Bs[b_row][b_nc + 1] = wmma::__float_to_tf32(bv.y);
        Bs[b_row][b_nc + 2] = wmma::__float_to_tf32(bv.z);
        Bs[b_row][b_nc + 3] = wmma::__float_to_tf32(bv.w);
        __syncthreads();

        #pragma unroll
        for (int ks = 0; ks < 16; ks += 8) {
            wmma::fragment<wmma::matrix_a, 16, 16, 8, wmma::precision::tf32, wmma::row_major> af;
            wmma::load_matrix_sync(af, &As[wm * 16][ks], 20);
            #pragma unroll
            for (int nf = 0; nf < 4; nf++) {
                wmma::fragment<wmma::matrix_b, 16, 16, 8, wmma::precision::tf32, wmma::row_major> bf;
                wmma::load_matrix_sync(bf, &Bs[ks][nf * 16], 68);
                wmma::mma_sync(acc[nf], af, bf, acc[nf]);
            }
        }
        __syncthreads();
    }

    float* base = &C[(size_t)(row0 + wm * 16) * D_ + col0];
    #pragma unroll
    for (int nf = 0; nf < 4; nf++)
        wmma::store_matrix_sync(base + nf * 16, acc[nf], D_, wmma::mem_row_major);
}

// ---------------- softmax + sampling-coordinate precompute ----------------
__global__ __launch_bounds__(256) void coords_softmax(
    const float* __restrict__ trajs, const float* __restrict__ centers,
    float4* __restrict__ scw)
{
    int gid = blockIdx.x * blockDim.x + threadIdx.x;
    if (gid >= ROWS_ * NH_ * NS_) return;
    int r = gid / (NH_ * NS_);
    int rem = gid - r * (NH_ * NS_);
    int h = rem / NS_;
    int s = rem - h * NS_;
    int b = r / NQ_;
    int q = r - b * NQ_;
    int a = q / M_;
    const float* tr = trajs + ((size_t)(((b * A_ + a) * M_ + (q - a * M_)) * NS_ + (NS_ - 1))) * 2;
    float cx = centers[(b * A_ + a) * 2 + 0];
    float cy = centers[(b * A_ + a) * 2 + 1];
    const float sc = 200.0f / 102.4f;
    float xb = (tr[0] + cx + 51.2f) * sc - 0.5f;
    float yb = (tr[1] + cy + 51.2f) * sc - 0.5f;

    const float* awp  = g_aw  + (size_t)r * 384 + h * (NS_ * NP_) + s * NP_;
    const float* offp = g_off + (size_t)r * 768 + h * (NS_ * NP_ * 2) + s * (NP_ * 2);
    float a0 = awp[0], a1 = awp[1], a2 = awp[2], a3 = awp[3];
    float mx = fmaxf(fmaxf(a0, a1), fmaxf(a2, a3));
    float e0 = expf(a0 - mx), e1 = expf(a1 - mx), e2 = expf(a2 - mx), e3 = expf(a3 - mx);
    float inv = 1.0f / (e0 + e1 + e2 + e3);
    float w[4] = {e0 * inv, e1 * inv, e2 * inv, e3 * inv};

    float4* out = scw + (((size_t)r * NS_ + s) * NH_ + h) * NP_;
    #pragma unroll
    for (int p = 0; p < 4; p++)
        out[p] = make_float4(xb + offp[2 * p], yb + offp[2 * p + 1], w[p], 0.0f);
}

// ---------------- deformable sampling (fp32 image) ----------------
__global__ __launch_bounds__(256) void sample_kernel(
    const float4* __restrict__ scw, float* __restrict__ outp)
{
    const int blk = blockIdx.x;          // r*NS + s
    const int r = blk / NS_;
    const int s = blk - r * NS_;
    const int b = r / NQ_;
    __shared__ float4 sh[NH_ * NP_];
    const int t = threadIdx.x;
    if (t < NH_ * NP_) sh[t] = scw[(size_t)blk * (NH_ * NP_) + t];
    __syncthreads();

    const int h = t >> 5, dh = t & 31;
    const float* img = g_vimg + (size_t)(b * NH_ + h) * V_ * DH_;
    float acc = 0.0f;
    #pragma unroll
    for (int p = 0; p < NP_; p++) {
        float4 s4 = sh[h * NP_ + p];
        float x = s4.x, y = s4.y, w = s4.z;
        float xf = floorf(x), yf = floorf(y);
        int x0 = (int)xf, y0 = (int)yf;
        float wx1 = x - xf, wy1 = y - yf;
        float wx0 = 1.0f - wx1, wy0 = 1.0f - wy1;
        bool xv0 = (x0 >= 0) & (x0 < WB_);
        bool xv1 = (x0 + 1 >= 0) & (x0 + 1 < WB_);
        bool yv0 = (y0 >= 0) & (y0 < HB_);
        bool yv1 = (y0 + 1 >= 0) & (y0 + 1 < HB_);
        float v00 = 0.f, v10 = 0.f, v01 = 0.f, v11 = 0.f;
        if (xv0 && yv0) v00 = img[((size_t)(y0 * WB_ + x0)) * DH_ + dh];
        if (xv1 && yv0) v10 = img[((size_t)(y0 * WB_ + x0 + 1)) * DH_ + dh];
        if (xv0 && yv1) v01 = img[((size_t)((y0 + 1) * WB_ + x0)) * DH_ + dh];
        if (xv1 && yv1) v11 = img[((size_t)((y0 + 1) * WB_ + x0 + 1)) * DH_ + dh];
        acc += w * (v00 * wx0 * wy0 + v10 * wx1 * wy0 + v01 * wx0 * wy1 + v11 * wx1 * wy1);
    }
    outp[(size_t)r * (NS_ * D_) + s * D_ + h * DH_ + dh] = acc;
}

// ---------------- LayerNorm + ReLU + residual (+ split-K reduction + bias) --------
__global__ __launch_bounds__(256) void ln_relu_res(
    const float* __restrict__ query, const float* __restrict__ bias,
    const float* __restrict__ gam, const float* __restrict__ bet,
    float* __restrict__ out)
{
    const int r = blockIdx.x;
    const int d = threadIdx.x;
    const size_t idx = (size_t)r * D_ + d;
    float v = g_opart[idx]
            + g_opart[(size_t)1 * ROWS_ * D_ + idx]
            + g_opart[(size_t)2 * ROWS_ * D_ + idx]
            + g_opart[(size_t)3 * ROWS_ * D_ + idx]
            + bias[d];
    float s1 = v, s2 = v * v;
    __shared__ float shs[8], shq[8];
    const int lane = d & 31, w = d >> 5;
    #pragma unroll
    for (int o = 16; o; o >>= 1) {
        s1 += __shfl_xor_sync(0xffffffffu, s1, o);
        s2 += __shfl_xor_sync(0xffffffffu, s2, o);
    }
    if (lane == 0) { shs[w] = s1; shq[w] = s2; }
    __syncthreads();
    if (d == 0) {
        float t1 = 0.f, t2 = 0.f;
        #pragma unroll
        for (int i = 0; i < 8; i++) { t1 += shs[i]; t2 += shq[i]; }
        shs[0] = t1 * (1.0f / D_);
        shq[0] = t2 * (1.0f / D_);
    }
    __syncthreads();
    float mu = shs[0];
    float var = shq[0] - mu * mu;
    float y = (v - mu) * rsqrtf(var + LN_EPS) * gam[d] + bet[d];
    y = fmaxf(y, 0.0f);
    out[idx] = y + query[idx];
}

// ---------------- launch ----------------
extern "C" void kernel_launch(void* const* d_in, const int* in_sizes, int n_in,
                              void* d_out, int out_size)
{
    const float* query      = (const float*)d_in[0];
    const float* query_pos  = (const float*)d_in[1];
    const float* value      = (const float*)d_in[2];
    const float* ref_trajs  = (const float*)d_in[3];
    const float* centers    = (const float*)d_in[4];
    const float* W_off      = (const float*)d_in[5];
    const float* b_off      = (const float*)d_in[6];
    const float* W_attn     = (const float*)d_in[7];
    const float* b_attn     = (const float*)d_in[8];
    const float* W_val      = (const float*)d_in[9];
    const float* b_val      = (const float*)d_in[10];
    const float* W_out      = (const float*)d_in[11];
    const float* b_out      = (const float*)d_in[12];
    const float* ln_g       = (const float*)d_in[13];
    const float* ln_b       = (const float*)d_in[14];
    float* out = (float*)d_out;

    float *offb, *awb, *samp;
    float4* scw;
    cudaGetSymbolAddress((void**)&offb, g_off);
    cudaGetSymbolAddress((void**)&awb,  g_aw);
    cudaGetSymbolAddress((void**)&scw,  g_scw);
    cudaGetSymbolAddress((void**)&samp, g_samp);

    // 1) value projection + layout transform (tf32 wmma, 128x64 tiles)
    gemm_val_wmma<<<dim3(4, (BS_ * V_) / 128), 256>>>(value, W_val, b_val);

    // 2) offset + attention projections (fp32 SIMT, unchanged)
    sgemm_bias<<<dim3(768 / 64, ROWS_ / 64), 256>>>(query, query_pos, W_off, b_off, offb, ROWS_, 768, 256);
    sgemm_bias<<<dim3(384 / 64, ROWS_ / 64), 256>>>(query, query_pos, W_attn, b_attn, awb, ROWS_, 384, 256);

    // 3) softmax + sampling coordinates
    coords_softmax<<<(ROWS_ * NH_ * NS_ + 255) / 256, 256>>>(ref_trajs, centers, scw);

    // 4) bilinear gather + attention-weighted sum
    sample_kernel<<<ROWS_ * NS_, 256>>>(scw, samp);

    // 5) output projection, split-K x4 (tf32 wmma, 128x64 tiles)
    gemm_out_splitk_wmma<<<dim3(D_ / 64, ROWS_ / 128, KSPLIT), 256>>>(W_out);

    // 6) split-K reduce + bias + LayerNorm + ReLU + residual
    ln_relu_res<<<ROWS_, 256>>>(query, b_out, ln_g, ln_b, out);
}

// round 16
// speedup vs baseline: 1.2679x; 1.0132x over previous
#include <cuda_runtime.h>
#include <mma.h>

using namespace nvcuda;

// ---------------- problem constants ----------------
#define D_     256
#define NH_    8
#define DH_    32
#define NS_    12
#define NP_    4
#define HB_    200
#define WB_    200
#define V_     (HB_*WB_)       // 40000
#define BS_    2
#define A_     256
#define M_     6
#define NQ_    (A_*M_)         // 1536
#define ROWS_  (BS_*NQ_)       // 3072
#define LN_EPS 1e-5f

#define KSPLIT 4               // split-K factor for the out-projection GEMM

// ---------------- device scratch (static, allocation-free) ----------------
__device__ __align__(16) float g_vimg[(size_t)BS_*NH_*V_*DH_];     // [b][h][pix][dh]
__device__ __align__(16) float g_off [(size_t)ROWS_*768];
__device__ __align__(16) float g_aw  [(size_t)ROWS_*384];
__device__ __align__(16) float4 g_scw[(size_t)ROWS_*NS_*NH_*NP_];  // (x, y, weight, pad)
__device__ __align__(16) float g_samp[(size_t)ROWS_*NS_*D_];       // (3072, 3072)
__device__ __align__(16) float g_opart[(size_t)KSPLIT*ROWS_*D_];   // split-K partials

// tf32-convert a float4 (values stay float-typed bit patterns)
__device__ __forceinline__ float4 cvt4(float4 v) {
    return make_float4(wmma::__float_to_tf32(v.x), wmma::__float_to_tf32(v.y),
                       wmma::__float_to_tf32(v.z), wmma::__float_to_tf32(v.w));
}

// ---------------- tf32 wmma query-projection GEMM: 128x64 tile, 4 frags/warp ----
// C = (A0 + A1) @ B + bias.  M=3072, K=256, N param (768/384). Bias preloaded.
__global__ __launch_bounds__(256) void gemm_qproj_wmma(
    const float* __restrict__ A0, const float* __restrict__ A1,
    const float* __restrict__ B, const float* __restrict__ bias,
    float* __restrict__ C, int N)
{
    __shared__ float As[128][20];
    __shared__ float Bs[16][68];

    const int tid = threadIdx.x;
    const int wm  = tid >> 5;

    const int row0 = blockIdx.y * 128;
    const int col0 = blockIdx.x * 64;

    const int a_row0 = tid >> 2, a_kc = (tid & 3) << 2;
    const int a_row1 = a_row0 + 64;
    const size_t a_base0 = (size_t)(row0 + a_row0) * 256;
    const size_t a_base1 = (size_t)(row0 + a_row1) * 256;
    const int b_row = tid >> 4, b_nc = (tid & 15) << 2;

    wmma::fragment<wmma::accumulator, 16, 16, 8, float> acc[4];
    {
        *reinterpret_cast<float4*>(&Bs[b_row][b_nc]) =
            *reinterpret_cast<const float4*>(&bias[col0 + b_nc]);
        __syncthreads();
        #pragma unroll
        for (int nf = 0; nf < 4; nf++)
            wmma::load_matrix_sync(acc[nf], &Bs[0][nf * 16], 68, wmma::mem_row_major);
        __syncthreads();
    }

    for (int k0 = 0; k0 < 256; k0 += 16) {
        float4 av0 = *reinterpret_cast<const float4*>(&A0[a_base0 + k0 + a_kc]);
        float4 av1 = *reinterpret_cast<const float4*>(&A0[a_base1 + k0 + a_kc]);
        float4 p0  = *reinterpret_cast<const float4*>(&A1[a_base0 + k0 + a_kc]);
        float4 p1  = *reinterpret_cast<const float4*>(&A1[a_base1 + k0 + a_kc]);
        av0.x += p0.x; av0.y += p0.y; av0.z += p0.z; av0.w += p0.w;
        av1.x += p1.x; av1.y += p1.y; av1.z += p1.z; av1.w += p1.w;
        *reinterpret_cast<float4*>(&As[a_row0][a_kc]) = cvt4(av0);
        *reinterpret_cast<float4*>(&As[a_row1][a_kc]) = cvt4(av1);
        float4 bv = *reinterpret_cast<const float4*>(&B[(size_t)(k0 + b_row) * N + col0 + b_nc]);
        *reinterpret_cast<float4*>(&Bs[b_row][b_nc]) = cvt4(bv);
        __syncthreads();

        #pragma unroll
        for (int ks = 0; ks < 16; ks += 8) {
            wmma::fragment<wmma::matrix_a, 16, 16, 8, wmma::precision::tf32, wmma::row_major> af;
            wmma::load_matrix_sync(af, &As[wm * 16][ks], 20);
            #pragma unroll
            for (int nf = 0; nf < 4; nf++) {
                wmma::fragment<wmma::matrix_b, 16, 16, 8, wmma::precision::tf32, wmma::row_major> bf;
                wmma::load_matrix_sync(bf, &Bs[ks][nf * 16], 68);
                wmma::mma_sync(acc[nf], af, bf, acc[nf]);
            }
        }
        __syncthreads();
    }

    float* base = &C[(size_t)(row0 + wm * 16) * N + col0];
    #pragma unroll
    for (int nf = 0; nf < 4; nf++)
        wmma::store_matrix_sync(base + nf * 16, acc[nf], N, wmma::mem_row_major);
}

// ---------------- tf32 wmma value-projection GEMM: 128x64 tile, 4 frags/warp ----
__global__ __launch_bounds__(256) void gemm_val_wmma(
    const float* __restrict__ value, const float* __restrict__ W,
    const float* __restrict__ bias)
{
    __shared__ float As[128][20];
    __shared__ float Bs[16][68];

    const int tid = threadIdx.x;
    const int wm  = tid >> 5;

    const int row0 = blockIdx.y * 128;
    const int col0 = blockIdx.x * 64;

    const int a_row0 = tid >> 2, a_kc = (tid & 3) << 2;
    const int a_row1 = a_row0 + 64;
    size_t a_base0, a_base1;
    {
        int g0 = row0 + a_row0, g1 = row0 + a_row1;
        int bb0 = (g0 >= V_) ? 1 : 0, bb1 = (g1 >= V_) ? 1 : 0;
        a_base0 = ((size_t)(g0 - bb0 * V_) * BS_ + bb0) * 256;
        a_base1 = ((size_t)(g1 - bb1 * V_) * BS_ + bb1) * 256;
    }
    const int b_row = tid >> 4, b_nc = (tid & 15) << 2;

    wmma::fragment<wmma::accumulator, 16, 16, 8, float> acc[4];
    {
        *reinterpret_cast<float4*>(&Bs[b_row][b_nc]) =
            *reinterpret_cast<const float4*>(&bias[col0 + b_nc]);
        __syncthreads();
        #pragma unroll
        for (int nf = 0; nf < 4; nf++)
            wmma::load_matrix_sync(acc[nf], &Bs[0][nf * 16], 68, wmma::mem_row_major);
        __syncthreads();
    }

    for (int k0 = 0; k0 < 256; k0 += 16) {
        float4 av0 = *reinterpret_cast<const float4*>(&value[a_base0 + k0 + a_kc]);
        float4 av1 = *reinterpret_cast<const float4*>(&value[a_base1 + k0 + a_kc]);
        *reinterpret_cast<float4*>(&As[a_row0][a_kc]) = cvt4(av0);
        *reinterpret_cast<float4*>(&As[a_row1][a_kc]) = cvt4(av1);
        float4 bv = *reinterpret_cast<const float4*>(&W[(size_t)(k0 + b_row) * 256 + col0 + b_nc]);
        *reinterpret_cast<float4*>(&Bs[b_row][b_nc]) = cvt4(bv);
        __syncthreads();

        #pragma unroll
        for (int ks = 0; ks < 16; ks += 8) {
            wmma::fragment<wmma::matrix_a, 16, 16, 8, wmma::precision::tf32, wmma::row_major> af;
            wmma::load_matrix_sync(af, &As[wm * 16][ks], 20);
            #pragma unroll
            for (int nf = 0; nf < 4; nf++) {
                wmma::fragment<wmma::matrix_b, 16, 16, 8, wmma::precision::tf32, wmma::row_major> bf;
                wmma::load_matrix_sync(bf, &Bs[ks][nf * 16], 68);
                wmma::mma_sync(acc[nf], af, bf, acc[nf]);
            }
        }
        __syncthreads();
    }

    const int gr = row0 + wm * 16;                 // 16-row bands never straddle b
    const int bb = (gr >= V_) ? 1 : 0;
    const int pix = gr - bb * V_;
    #pragma unroll
    for (int nf = 0; nf < 4; nf++) {
        const int gc = col0 + nf * 16;
        const int h = gc >> 5, dh = gc & 31;        // dh in {0,16}
        float* base = &g_vimg[(((size_t)(bb * NH_ + h)) * V_ + pix) * DH_ + dh];
        wmma::store_matrix_sync(base, acc[nf], DH_, wmma::mem_row_major);
    }
}

// ---------------- tf32 wmma split-K out-projection: 128x64 tile, 4 frags/warp ----
__global__ __launch_bounds__(256) void gemm_out_splitk_wmma(
    const float* __restrict__ B)
{
    __shared__ float As[128][20];
    __shared__ float Bs[16][68];

    const int tid = threadIdx.x;
    const int wm  = tid >> 5;

    const int row0 = blockIdx.y * 128;
    const int col0 = blockIdx.x * 64;
    const int slice = blockIdx.z;
    const int kbase = slice * (3072 / KSPLIT);

    const int a_row0 = tid >> 2, a_kc = (tid & 3) << 2;
    const int a_row1 = a_row0 + 64;
    const int b_row = tid >> 4, b_nc = (tid & 15) << 2;
    float* __restrict__ C = g_opart + (size_t)slice * ROWS_ * D_;

    wmma::fragment<wmma::accumulator, 16, 16, 8, float> acc[4];
    #pragma unroll
    for (int nf = 0; nf < 4; nf++) wmma::fill_fragment(acc[nf], 0.0f);

    for (int kk = 0; kk < 3072 / KSPLIT; kk += 16) {
        const int k0 = kbase + kk;
        float4 av0 = *reinterpret_cast<const float4*>(
            &g_samp[(size_t)(row0 + a_row0) * 3072 + k0 + a_kc]);
        float4 av1 = *reinterpret_cast<const float4*>(
            &g_samp[(size_t)(row0 + a_row1) * 3072 + k0 + a_kc]);
        *reinterpret_cast<float4*>(&As[a_row0][a_kc]) = cvt4(av0);
        *reinterpret_cast<float4*>(&As[a_row1][a_kc]) = cvt4(av1);
        float4 bv = *reinterpret_cast<const float4*>(&B[(size_t)(k0 + b_row) * 256 + col0 + b_nc]);
        *reinterpret_cast<float4*>(&Bs[b_row][b_nc]) = cvt4(bv);
        __syncthreads();

        #pragma unroll
        for (int ks = 0; ks < 16; ks += 8) {
            wmma::fragment<wmma::matrix_a, 16, 16, 8, wmma::precision::tf32, wmma::row_major> af;
            wmma::load_matrix_sync(af, &As[wm * 16][ks], 20);
            #pragma unroll
            for (int nf = 0; nf < 4; nf++) {
                wmma::fragment<wmma::matrix_b, 16, 16, 8, wmma::precision::tf32, wmma::row_major> bf;
                wmma::load_matrix_sync(bf, &Bs[ks][nf * 16], 68);
                wmma::mma_sync(acc[nf], af, bf, acc[nf]);
            }
        }
        __syncthreads();
    }

    float* base = &C[(size_t)(row0 + wm * 16) * D_ + col0];
    #pragma unroll
    for (int nf = 0; nf < 4; nf++)
        wmma::store_matrix_sync(base + nf * 16, acc[nf], D_, wmma::mem_row_major);
}

// ---------------- softmax + sampling-coordinate precompute ----------------
__global__ __launch_bounds__(256) void coords_softmax(
    const float* __restrict__ trajs, const float* __restrict__ centers,
    float4* __restrict__ scw)
{
    int gid = blockIdx.x * blockDim.x + threadIdx.x;
    if (gid >= ROWS_ * NH_ * NS_) return;
    int r = gid / (NH_ * NS_);
    int rem = gid - r * (NH_ * NS_);
    int h = rem / NS_;
    int s = rem - h * NS_;
    int b = r / NQ_;
    int q = r - b * NQ_;
    int a = q / M_;
    const float* tr = trajs + ((size_t)(((b * A_ + a) * M_ + (q - a * M_)) * NS_ + (NS_ - 1))) * 2;
    float cx = centers[(b * A_ + a) * 2 + 0];
    float cy = centers[(b * A_ + a) * 2 + 1];
    const float sc = 200.0f / 102.4f;
    float xb = (tr[0] + cx + 51.2f) * sc - 0.5f;
    float yb = (tr[1] + cy + 51.2f) * sc - 0.5f;

    const float* awp  = g_aw  + (size_t)r * 384 + h * (NS_ * NP_) + s * NP_;
    const float* offp = g_off + (size_t)r * 768 + h * (NS_ * NP_ * 2) + s * (NP_ * 2);
    float a0 = awp[0], a1 = awp[1], a2 = awp[2], a3 = awp[3];
    float mx = fmaxf(fmaxf(a0, a1), fmaxf(a2, a3));
    float e0 = expf(a0 - mx), e1 = expf(a1 - mx), e2 = expf(a2 - mx), e3 = expf(a3 - mx);
    float inv = 1.0f / (e0 + e1 + e2 + e3);
    float w[4] = {e0 * inv, e1 * inv, e2 * inv, e3 * inv};

    float4* out = scw + (((size_t)r * NS_ + s) * NH_ + h) * NP_;
    #pragma unroll
    for (int p = 0; p < 4; p++)
        out[p] = make_float4(xb + offp[2 * p], yb + offp[2 * p + 1], w[p], 0.0f);
}

// ---------------- deformable sampling (fp32 image) ----------------
__global__ __launch_bounds__(256) void sample_kernel(
    const float4* __restrict__ scw, float* __restrict__ outp)
{
    const int blk = blockIdx.x;          // r*NS + s
    const int r = blk / NS_;
    const int s = blk - r * NS_;
    const int b = r / NQ_;
    __shared__ float4 sh[NH_ * NP_];
    const int t = threadIdx.x;
    if (t < NH_ * NP_) sh[t] = scw[(size_t)blk * (NH_ * NP_) + t];
    __syncthreads();

    const int h = t >> 5, dh = t & 31;
    const float* img = g_vimg + (size_t)(b * NH_ + h) * V_ * DH_;
    float acc = 0.0f;
    #pragma unroll
    for (int p = 0; p < NP_; p++) {
        float4 s4 = sh[h * NP_ + p];
        float x = s4.x, y = s4.y, w = s4.z;
        float xf = floorf(x), yf = floorf(y);
        int x0 = (int)xf, y0 = (int)yf;
        float wx1 = x - xf, wy1 = y - yf;
        float wx0 = 1.0f - wx1, wy0 = 1.0f - wy1;
        bool xv0 = (x0 >= 0) & (x0 < WB_);
        bool xv1 = (x0 + 1 >= 0) & (x0 + 1 < WB_);
        bool yv0 = (y0 >= 0) & (y0 < HB_);
        bool yv1 = (y0 + 1 >= 0) & (y0 + 1 < HB_);
        float v00 = 0.f, v10 = 0.f, v01 = 0.f, v11 = 0.f;
        if (xv0 && yv0) v00 = img[((size_t)(y0 * WB_ + x0)) * DH_ + dh];
        if (xv1 && yv0) v10 = img[((size_t)(y0 * WB_ + x0 + 1)) * DH_ + dh];
        if (xv0 && yv1) v01 = img[((size_t)((y0 + 1) * WB_ + x0)) * DH_ + dh];
        if (xv1 && yv1) v11 = img[((size_t)((y0 + 1) * WB_ + x0 + 1)) * DH_ + dh];
        acc += w * (v00 * wx0 * wy0 + v10 * wx1 * wy0 + v01 * wx0 * wy1 + v11 * wx1 * wy1);
    }
    outp[(size_t)r * (NS_ * D_) + s * D_ + h * DH_ + dh] = acc;
}

// ---------------- LayerNorm + ReLU + residual (+ split-K reduction + bias) --------
__global__ __launch_bounds__(256) void ln_relu_res(
    const float* __restrict__ query, const float* __restrict__ bias,
    const float* __restrict__ gam, const float* __restrict__ bet,
    float* __restrict__ out)
{
    const int r = blockIdx.x;
    const int d = threadIdx.x;
    const size_t idx = (size_t)r * D_ + d;
    float v = g_opart[idx]
            + g_opart[(size_t)1 * ROWS_ * D_ + idx]
            + g_opart[(size_t)2 * ROWS_ * D_ + idx]
            + g_opart[(size_t)3 * ROWS_ * D_ + idx]
            + bias[d];
    float s1 = v, s2 = v * v;
    __shared__ float shs[8], shq[8];
    const int lane = d & 31, w = d >> 5;
    #pragma unroll
    for (int o = 16; o; o >>= 1) {
        s1 += __shfl_xor_sync(0xffffffffu, s1, o);
        s2 += __shfl_xor_sync(0xffffffffu, s2, o);
    }
    if (lane == 0) { shs[w] = s1; shq[w] = s2; }
    __syncthreads();
    if (d == 0) {
        float t1 = 0.f, t2 = 0.f;
        #pragma unroll
        for (int i = 0; i < 8; i++) { t1 += shs[i]; t2 += shq[i]; }
        shs[0] = t1 * (1.0f / D_);
        shq[0] = t2 * (1.0f / D_);
    }
    __syncthreads();
    float mu = shs[0];
    float var = shq[0] - mu * mu;
    float y = (v - mu) * rsqrtf(var + LN_EPS) * gam[d] + bet[d];
    y = fmaxf(y, 0.0f);
    out[idx] = y + query[idx];
}

// ---------------- launch ----------------
extern "C" void kernel_launch(void* const* d_in, const int* in_sizes, int n_in,
                              void* d_out, int out_size)
{
    const float* query      = (const float*)d_in[0];
    const float* query_pos  = (const float*)d_in[1];
    const float* value      = (const float*)d_in[2];
    const float* ref_trajs  = (const float*)d_in[3];
    const float* centers    = (const float*)d_in[4];
    const float* W_off      = (const float*)d_in[5];
    const float* b_off      = (const float*)d_in[6];
    const float* W_attn     = (const float*)d_in[7];
    const float* b_attn     = (const float*)d_in[8];
    const float* W_val      = (const float*)d_in[9];
    const float* b_val      = (const float*)d_in[10];
    const float* W_out      = (const float*)d_in[11];
    const float* b_out      = (const float*)d_in[12];
    const float* ln_g       = (const float*)d_in[13];
    const float* ln_b       = (const float*)d_in[14];
    float* out = (float*)d_out;

    float *offb, *awb, *samp;
    float4* scw;
    cudaGetSymbolAddress((void**)&offb, g_off);
    cudaGetSymbolAddress((void**)&awb,  g_aw);
    cudaGetSymbolAddress((void**)&scw,  g_scw);
    cudaGetSymbolAddress((void**)&samp, g_samp);

    // 1) value projection + layout transform (tf32 wmma, 128x64 tiles)
    gemm_val_wmma<<<dim3(4, (BS_ * V_) / 128), 256>>>(value, W_val, b_val);

    // 2) offset + attention projections (tf32 wmma, 128x64 tiles)
    gemm_qproj_wmma<<<dim3(768 / 64, ROWS_ / 128), 256>>>(query, query_pos, W_off, b_off, offb, 768);
    gemm_qproj_wmma<<<dim3(384 / 64, ROWS_ / 128), 256>>>(query, query_pos, W_attn, b_attn, awb, 384);

    // 3) softmax + sampling coordinates
    coords_softmax<<<(ROWS_ * NH_ * NS_ + 255) / 256, 256>>>(ref_trajs, centers, scw);

    // 4) bilinear gather + attention-weighted sum
    sample_kernel<<<ROWS_ * NS_, 256>>>(scw, samp);

    // 5) output projection, split-K x4 (tf32 wmma, 128x64 tiles)
    gemm_out_splitk_wmma<<<dim3(D_ / 64, ROWS_ / 128, KSPLIT), 256>>>(W_out);

    // 6) split-K reduce + bias + LayerNorm + ReLU + residual
    ln_relu_res<<<ROWS_, 256>>>(query, b_out, ln_g, ln_b, out);
}

// round 17
// speedup vs baseline: 1.3921x; 1.0980x over previous
#include <cuda_runtime.h>
#include <cuda_pipeline.h>
#include <mma.h>

using namespace nvcuda;

// ---------------- problem constants ----------------
#define D_     256
#define NH_    8
#define DH_    32
#define NS_    12
#define NP_    4
#define HB_    200
#define WB_    200
#define V_     (HB_*WB_)       // 40000
#define BS_    2
#define A_     256
#define M_     6
#define NQ_    (A_*M_)         // 1536
#define ROWS_  (BS_*NQ_)       // 3072
#define LN_EPS 1e-5f

#define KSPLIT 4               // split-K factor for the out-projection GEMM

// ---------------- device scratch (static, allocation-free) ----------------
__device__ __align__(16) float g_vimg[(size_t)BS_*NH_*V_*DH_];     // [b][h][pix][dh]
__device__ __align__(16) float g_off [(size_t)ROWS_*768];
__device__ __align__(16) float g_aw  [(size_t)ROWS_*384];
__device__ __align__(16) float4 g_scw[(size_t)ROWS_*NS_*NH_*NP_];  // (x, y, weight, pad)
__device__ __align__(16) float g_samp[(size_t)ROWS_*NS_*D_];       // (3072, 3072)
__device__ __align__(16) float g_opart[(size_t)KSPLIT*ROWS_*D_];   // split-K partials

// tf32-convert a float4 (qproj path only; big GEMMs rely on HW truncation)
__device__ __forceinline__ float4 cvt4(float4 v) {
    return make_float4(wmma::__float_to_tf32(v.x), wmma::__float_to_tf32(v.y),
                       wmma::__float_to_tf32(v.z), wmma::__float_to_tf32(v.w));
}

// ---------------- tf32 wmma query-projection GEMM (register-staged; unchanged) ----
__global__ __launch_bounds__(256) void gemm_qproj_wmma(
    const float* __restrict__ A0, const float* __restrict__ A1,
    const float* __restrict__ B, const float* __restrict__ bias,
    float* __restrict__ C, int N)
{
    __shared__ float As[128][20];
    __shared__ float Bs[16][68];

    const int tid = threadIdx.x;
    const int wm  = tid >> 5;

    const int row0 = blockIdx.y * 128;
    const int col0 = blockIdx.x * 64;

    const int a_row0 = tid >> 2, a_kc = (tid & 3) << 2;
    const int a_row1 = a_row0 + 64;
    const size_t a_base0 = (size_t)(row0 + a_row0) * 256;
    const size_t a_base1 = (size_t)(row0 + a_row1) * 256;
    const int b_row = tid >> 4, b_nc = (tid & 15) << 2;

    wmma::fragment<wmma::accumulator, 16, 16, 8, float> acc[4];
    {
        *reinterpret_cast<float4*>(&Bs[b_row][b_nc]) =
            *reinterpret_cast<const float4*>(&bias[col0 + b_nc]);
        __syncthreads();
        #pragma unroll
        for (int nf = 0; nf < 4; nf++)
            wmma::load_matrix_sync(acc[nf], &Bs[0][nf * 16], 68, wmma::mem_row_major);
        __syncthreads();
    }

    for (int k0 = 0; k0 < 256; k0 += 16) {
        float4 av0 = *reinterpret_cast<const float4*>(&A0[a_base0 + k0 + a_kc]);
        float4 av1 = *reinterpret_cast<const float4*>(&A0[a_base1 + k0 + a_kc]);
        float4 p0  = *reinterpret_cast<const float4*>(&A1[a_base0 + k0 + a_kc]);
        float4 p1  = *reinterpret_cast<const float4*>(&A1[a_base1 + k0 + a_kc]);
        av0.x += p0.x; av0.y += p0.y; av0.z += p0.z; av0.w += p0.w;
        av1.x += p1.x; av1.y += p1.y; av1.z += p1.z; av1.w += p1.w;
        *reinterpret_cast<float4*>(&As[a_row0][a_kc]) = cvt4(av0);
        *reinterpret_cast<float4*>(&As[a_row1][a_kc]) = cvt4(av1);
        float4 bv = *reinterpret_cast<const float4*>(&B[(size_t)(k0 + b_row) * N + col0 + b_nc]);
        *reinterpret_cast<float4*>(&Bs[b_row][b_nc]) = cvt4(bv);
        __syncthreads();

        #pragma unroll
        for (int ks = 0; ks < 16; ks += 8) {
            wmma::fragment<wmma::matrix_a, 16, 16, 8, wmma::precision::tf32, wmma::row_major> af;
            wmma::load_matrix_sync(af, &As[wm * 16][ks], 20);
            #pragma unroll
            for (int nf = 0; nf < 4; nf++) {
                wmma::fragment<wmma::matrix_b, 16, 16, 8, wmma::precision::tf32, wmma::row_major> bf;
                wmma::load_matrix_sync(bf, &Bs[ks][nf * 16], 68);
                wmma::mma_sync(acc[nf], af, bf, acc[nf]);
            }
        }
        __syncthreads();
    }

    float* base = &C[(size_t)(row0 + wm * 16) * N + col0];
    #pragma unroll
    for (int nf = 0; nf < 4; nf++)
        wmma::store_matrix_sync(base + nf * 16, acc[nf], N, wmma::mem_row_major);
}

// ---------------- tf32 wmma value-projection GEMM, cp.async double-buffered ----
// 128x64 tile; fp32 bits staged raw (HW truncates to tf32). Direct g_vimg scatter.
__global__ __launch_bounds__(256) void gemm_val_wmma(
    const float* __restrict__ value, const float* __restrict__ W,
    const float* __restrict__ bias)
{
    __shared__ float As[2][128][20];
    __shared__ float Bs[2][16][68];

    const int tid = threadIdx.x;
    const int wm  = tid >> 5;

    const int row0 = blockIdx.y * 128;
    const int col0 = blockIdx.x * 64;

    const int a_row0 = tid >> 2, a_kc = (tid & 3) << 2;
    const int a_row1 = a_row0 + 64;
    size_t a_base0, a_base1;
    {
        int g0 = row0 + a_row0, g1 = row0 + a_row1;
        int bb0 = (g0 >= V_) ? 1 : 0, bb1 = (g1 >= V_) ? 1 : 0;
        a_base0 = ((size_t)(g0 - bb0 * V_) * BS_ + bb0) * 256;
        a_base1 = ((size_t)(g1 - bb1 * V_) * BS_ + bb1) * 256;
    }
    const int b_row = tid >> 4, b_nc = (tid & 15) << 2;

    wmma::fragment<wmma::accumulator, 16, 16, 8, float> acc[4];
    {
        *reinterpret_cast<float4*>(&Bs[0][b_row][b_nc]) =
            *reinterpret_cast<const float4*>(&bias[col0 + b_nc]);
        __syncthreads();
        #pragma unroll
        for (int nf = 0; nf < 4; nf++)
            wmma::load_matrix_sync(acc[nf], &Bs[0][0][nf * 16], 68, wmma::mem_row_major);
        __syncthreads();
    }

    const int NITER = 256 / 16;
    // prologue: stage tile 0 into buffer 0
    __pipeline_memcpy_async(&As[0][a_row0][a_kc], &value[a_base0 + a_kc], 16);
    __pipeline_memcpy_async(&As[0][a_row1][a_kc], &value[a_base1 + a_kc], 16);
    __pipeline_memcpy_async(&Bs[0][b_row][b_nc], &W[(size_t)b_row * 256 + col0 + b_nc], 16);
    __pipeline_commit();

    for (int it = 0; it < NITER; it++) {
        const int cur = it & 1;
        if (it + 1 < NITER) {
            const int nxt = (it + 1) & 1;
            const int k1 = (it + 1) * 16;
            __pipeline_memcpy_async(&As[nxt][a_row0][a_kc], &value[a_base0 + k1 + a_kc], 16);
            __pipeline_memcpy_async(&As[nxt][a_row1][a_kc], &value[a_base1 + k1 + a_kc], 16);
            __pipeline_memcpy_async(&Bs[nxt][b_row][b_nc], &W[(size_t)(k1 + b_row) * 256 + col0 + b_nc], 16);
            __pipeline_commit();
            __pipeline_wait_prior(1);
        } else {
            __pipeline_wait_prior(0);
        }
        __syncthreads();

        #pragma unroll
        for (int ks = 0; ks < 16; ks += 8) {
            wmma::fragment<wmma::matrix_a, 16, 16, 8, wmma::precision::tf32, wmma::row_major> af;
            wmma::load_matrix_sync(af, &As[cur][wm * 16][ks], 20);
            #pragma unroll
            for (int nf = 0; nf < 4; nf++) {
                wmma::fragment<wmma::matrix_b, 16, 16, 8, wmma::precision::tf32, wmma::row_major> bf;
                wmma::load_matrix_sync(bf, &Bs[cur][ks][nf * 16], 68);
                wmma::mma_sync(acc[nf], af, bf, acc[nf]);
            }
        }
        __syncthreads();
    }

    const int gr = row0 + wm * 16;                 // 16-row bands never straddle b
    const int bb = (gr >= V_) ? 1 : 0;
    const int pix = gr - bb * V_;
    #pragma unroll
    for (int nf = 0; nf < 4; nf++) {
        const int gc = col0 + nf * 16;
        const int h = gc >> 5, dh = gc & 31;        // dh in {0,16}
        float* base = &g_vimg[(((size_t)(bb * NH_ + h)) * V_ + pix) * DH_ + dh];
        wmma::store_matrix_sync(base, acc[nf], DH_, wmma::mem_row_major);
    }
}

// ---------------- tf32 wmma split-K out-projection, cp.async double-buffered ----
__global__ __launch_bounds__(256) void gemm_out_splitk_wmma(
    const float* __restrict__ B)
{
    __shared__ float As[2][128][20];
    __shared__ float Bs[2][16][68];

    const int tid = threadIdx.x;
    const int wm  = tid >> 5;

    const int row0 = blockIdx.y * 128;
    const int col0 = blockIdx.x * 64;
    const int slice = blockIdx.z;
    const int kbase = slice * (3072 / KSPLIT);

    const int a_row0 = tid >> 2, a_kc = (tid & 3) << 2;
    const int a_row1 = a_row0 + 64;
    const int b_row = tid >> 4, b_nc = (tid & 15) << 2;
    float* __restrict__ C = g_opart + (size_t)slice * ROWS_ * D_;

    wmma::fragment<wmma::accumulator, 16, 16, 8, float> acc[4];
    #pragma unroll
    for (int nf = 0; nf < 4; nf++) wmma::fill_fragment(acc[nf], 0.0f);

    const int NITER = (3072 / KSPLIT) / 16;   // 48
    __pipeline_memcpy_async(&As[0][a_row0][a_kc],
                            &g_samp[(size_t)(row0 + a_row0) * 3072 + kbase + a_kc], 16);
    __pipeline_memcpy_async(&As[0][a_row1][a_kc],
                            &g_samp[(size_t)(row0 + a_row1) * 3072 + kbase + a_kc], 16);
    __pipeline_memcpy_async(&Bs[0][b_row][b_nc],
                            &B[(size_t)(kbase + b_row) * 256 + col0 + b_nc], 16);
    __pipeline_commit();

    for (int it = 0; it < NITER; it++) {
        const int cur = it & 1;
        if (it + 1 < NITER) {
            const int nxt = (it + 1) & 1;
            const int k1 = kbase + (it + 1) * 16;
            __pipeline_memcpy_async(&As[nxt][a_row0][a_kc],
                                    &g_samp[(size_t)(row0 + a_row0) * 3072 + k1 + a_kc], 16);
            __pipeline_memcpy_async(&As[nxt][a_row1][a_kc],
                                    &g_samp[(size_t)(row0 + a_row1) * 3072 + k1 + a_kc], 16);
            __pipeline_memcpy_async(&Bs[nxt][b_row][b_nc],
                                    &B[(size_t)(k1 + b_row) * 256 + col0 + b_nc], 16);
            __pipeline_commit();
            __pipeline_wait_prior(1);
        } else {
            __pipeline_wait_prior(0);
        }
        __syncthreads();

        #pragma unroll
        for (int ks = 0; ks < 16; ks += 8) {
            wmma::fragment<wmma::matrix_a, 16, 16, 8, wmma::precision::tf32, wmma::row_major> af;
            wmma::load_matrix_sync(af, &As[cur][wm * 16][ks], 20);
            #pragma unroll
            for (int nf = 0; nf < 4; nf++) {
                wmma::fragment<wmma::matrix_b, 16, 16, 8, wmma::precision::tf32, wmma::row_major> bf;
                wmma::load_matrix_sync(bf, &Bs[cur][ks][nf * 16], 68);
                wmma::mma_sync(acc[nf], af, bf, acc[nf]);
            }
        }
        __syncthreads();
    }

    float* base = &C[(size_t)(row0 + wm * 16) * D_ + col0];
    #pragma unroll
    for (int nf = 0; nf < 4; nf++)
        wmma::store_matrix_sync(base + nf * 16, acc[nf], D_, wmma::mem_row_major);
}

// ---------------- softmax + sampling-coordinate precompute ----------------
__global__ __launch_bounds__(256) void coords_softmax(
    const float* __restrict__ trajs, const float* __restrict__ centers,
    float4* __restrict__ scw)
{
    int gid = blockIdx.x * blockDim.x + threadIdx.x;
    if (gid >= ROWS_ * NH_ * NS_) return;
    int r = gid / (NH_ * NS_);
    int rem = gid - r * (NH_ * NS_);
    int h = rem / NS_;
    int s = rem - h * NS_;
    int b = r / NQ_;
    int q = r - b * NQ_;
    int a = q / M_;
    const float* tr = trajs + ((size_t)(((b * A_ + a) * M_ + (q - a * M_)) * NS_ + (NS_ - 1))) * 2;
    float cx = centers[(b * A_ + a) * 2 + 0];
    float cy = centers[(b * A_ + a) * 2 + 1];
    const float sc = 200.0f / 102.4f;
    float xb = (tr[0] + cx + 51.2f) * sc - 0.5f;
    float yb = (tr[1] + cy + 51.2f) * sc - 0.5f;

    const float* awp  = g_aw  + (size_t)r * 384 + h * (NS_ * NP_) + s * NP_;
    const float* offp = g_off + (size_t)r * 768 + h * (NS_ * NP_ * 2) + s * (NP_ * 2);
    float a0 = awp[0], a1 = awp[1], a2 = awp[2], a3 = awp[3];
    float mx = fmaxf(fmaxf(a0, a1), fmaxf(a2, a3));
    float e0 = expf(a0 - mx), e1 = expf(a1 - mx), e2 = expf(a2 - mx), e3 = expf(a3 - mx);
    float inv = 1.0f / (e0 + e1 + e2 + e3);
    float w[4] = {e0 * inv, e1 * inv, e2 * inv, e3 * inv};

    float4* out = scw + (((size_t)r * NS_ + s) * NH_ + h) * NP_;
    #pragma unroll
    for (int p = 0; p < 4; p++)
        out[p] = make_float4(xb + offp[2 * p], yb + offp[2 * p + 1], w[p], 0.0f);
}

// ---------------- deformable sampling (fp32 image) ----------------
__global__ __launch_bounds__(256) void sample_kernel(
    const float4* __restrict__ scw, float* __restrict__ outp)
{
    const int blk = blockIdx.x;          // r*NS + s
    const int r = blk / NS_;
    const int s = blk - r * NS_;
    const int b = r / NQ_;
    __shared__ float4 sh[NH_ * NP_];
    const int t = threadIdx.x;
    if (t < NH_ * NP_) sh[t] = scw[(size_t)blk * (NH_ * NP_) + t];
    __syncthreads();

    const int h = t >> 5, dh = t & 31;
    const float* img = g_vimg + (size_t)(b * NH_ + h) * V_ * DH_;
    float acc = 0.0f;
    #pragma unroll
    for (int p = 0; p < NP_; p++) {
        float4 s4 = sh[h * NP_ + p];
        float x = s4.x, y = s4.y, w = s4.z;
        float xf = floorf(x), yf = floorf(y);
        int x0 = (int)xf, y0 = (int)yf;
        float wx1 = x - xf, wy1 = y - yf;
        float wx0 = 1.0f - wx1, wy0 = 1.0f - wy1;
        bool xv0 = (x0 >= 0) & (x0 < WB_);
        bool xv1 = (x0 + 1 >= 0) & (x0 + 1 < WB_);
        bool yv0 = (y0 >= 0) & (y0 < HB_);
        bool yv1 = (y0 + 1 >= 0) & (y0 + 1 < HB_);
        float v00 = 0.f, v10 = 0.f, v01 = 0.f, v11 = 0.f;
        if (xv0 && yv0) v00 = img[((size_t)(y0 * WB_ + x0)) * DH_ + dh];
        if (xv1 && yv0) v10 = img[((size_t)(y0 * WB_ + x0 + 1)) * DH_ + dh];
        if (xv0 && yv1) v01 = img[((size_t)((y0 + 1) * WB_ + x0)) * DH_ + dh];
        if (xv1 && yv1) v11 = img[((size_t)((y0 + 1) * WB_ + x0 + 1)) * DH_ + dh];
        acc += w * (v00 * wx0 * wy0 + v10 * wx1 * wy0 + v01 * wx0 * wy1 + v11 * wx1 * wy1);
    }
    outp[(size_t)r * (NS_ * D_) + s * D_ + h * DH_ + dh] = acc;
}

// ---------------- LayerNorm + ReLU + residual (+ split-K reduction + bias) --------
__global__ __launch_bounds__(256) void ln_relu_res(
    const float* __restrict__ query, const float* __restrict__ bias,
    const float* __restrict__ gam, const float* __restrict__ bet,
    float* __restrict__ out)
{
    const int r = blockIdx.x;
    const int d = threadIdx.x;
    const size_t idx = (size_t)r * D_ + d;
    float v = g_opart[idx]
            + g_opart[(size_t)1 * ROWS_ * D_ + idx]
            + g_opart[(size_t)2 * ROWS_ * D_ + idx]
            + g_opart[(size_t)3 * ROWS_ * D_ + idx]
            + bias[d];
    float s1 = v, s2 = v * v;
    __shared__ float shs[8], shq[8];
    const int lane = d & 31, w = d >> 5;
    #pragma unroll
    for (int o = 16; o; o >>= 1) {
        s1 += __shfl_xor_sync(0xffffffffu, s1, o);
        s2 += __shfl_xor_sync(0xffffffffu, s2, o);
    }
    if (lane == 0) { shs[w] = s1; shq[w] = s2; }
    __syncthreads();
    if (d == 0) {
        float t1 = 0.f, t2 = 0.f;
        #pragma unroll
        for (int i = 0; i < 8; i++) { t1 += shs[i]; t2 += shq[i]; }
        shs[0] = t1 * (1.0f / D_);
        shq[0] = t2 * (1.0f / D_);
    }
    __syncthreads();
    float mu = shs[0];
    float var = shq[0] - mu * mu;
    float y = (v - mu) * rsqrtf(var + LN_EPS) * gam[d] + bet[d];
    y = fmaxf(y, 0.0f);
    out[idx] = y + query[idx];
}

// ---------------- launch ----------------
extern "C" void kernel_launch(void* const* d_in, const int* in_sizes, int n_in,
                              void* d_out, int out_size)
{
    const float* query      = (const float*)d_in[0];
    const float* query_pos  = (const float*)d_in[1];
    const float* value      = (const float*)d_in[2];
    const float* ref_trajs  = (const float*)d_in[3];
    const float* centers    = (const float*)d_in[4];
    const float* W_off      = (const float*)d_in[5];
    const float* b_off      = (const float*)d_in[6];
    const float* W_attn     = (const float*)d_in[7];
    const float* b_attn     = (const float*)d_in[8];
    const float* W_val      = (const float*)d_in[9];
    const float* b_val      = (const float*)d_in[10];
    const float* W_out      = (const float*)d_in[11];
    const float* b_out      = (const float*)d_in[12];
    const float* ln_g       = (const float*)d_in[13];
    const float* ln_b       = (const float*)d_in[14];
    float* out = (float*)d_out;

    float *offb, *awb, *samp;
    float4* scw;
    cudaGetSymbolAddress((void**)&offb, g_off);
    cudaGetSymbolAddress((void**)&awb,  g_aw);
    cudaGetSymbolAddress((void**)&scw,  g_scw);
    cudaGetSymbolAddress((void**)&samp, g_samp);

    // 1) value projection + layout transform (tf32 wmma + cp.async)
    gemm_val_wmma<<<dim3(4, (BS_ * V_) / 128), 256>>>(value, W_val, b_val);

    // 2) offset + attention projections (tf32 wmma, register-staged)
    gemm_qproj_wmma<<<dim3(768 / 64, ROWS_ / 128), 256>>>(query, query_pos, W_off, b_off, offb, 768);
    gemm_qproj_wmma<<<dim3(384 / 64, ROWS_ / 128), 256>>>(query, query_pos, W_attn, b_attn, awb, 384);

    // 3) softmax + sampling coordinates
    coords_softmax<<<(ROWS_ * NH_ * NS_ + 255) / 256, 256>>>(ref_trajs, centers, scw);

    // 4) bilinear gather + attention-weighted sum
    sample_kernel<<<ROWS_ * NS_, 256>>>(scw, samp);

    // 5) output projection, split-K x4 (tf32 wmma + cp.async)
    gemm_out_splitk_wmma<<<dim3(D_ / 64, ROWS_ / 128, KSPLIT), 256>>>(W_out);

    // 6) split-K reduce + bias + LayerNorm + ReLU + residual
    ln_relu_res<<<ROWS_, 256>>>(query, b_out, ln_g, ln_b, out);
}